// round 11
// baseline (speedup 1.0000x reference)
#include <cuda_runtime.h>
#include <cuda_fp16.h>
#include <math.h>
#include <stdint.h>

#define NPTS   32768
#define NEDGE  524288
#define NBATCH 2
#define HID    64
#define LIFTD  256
#define NLAYER 4

// ---------------- scratch ----------------
__device__ float    d_h[NBATCH * NPTS * HID];
__device__ uint32_t d_Ah[NBATCH * NPTS * 32];   // half2-packed A
__device__ uint32_t d_Pdh[NPTS * 32];           // half2-packed Pd
__device__ float    d_agg[NBATCH * NPTS * HID];
__device__ float    d_invc[NPTS];
__device__ int      d_deg[NPTS];
__device__ int      d_cursor[NPTS];
__device__ int      d_ssrc[NEDGE];
__device__ int      d_sdst[NEDGE];
__device__ int      d_is64;

// fast tanh-form gelu (fp32): HW tanh.approx, ~6 instructions.
__device__ __forceinline__ float gelu_fast(float x) {
    float x2 = x * x;
    float inner = x * fmaf(0.0356774081f, x2, 0.7978845608f);
    float t;
    asm("tanh.approx.f32 %0, %1;" : "=f"(t) : "f"(inner));
    float hx = 0.5f * x;
    return fmaf(hx, t, hx);
}
// packed half2 tanh-form gelu: tanh.approx.f16x2, ~5 instructions for 2 values.
__device__ __forceinline__ uint32_t gelu_h2(uint32_t xu) {
    __half2 x = *(__half2*)&xu;
    const __half2 c1 = __floats2half2_rn(0.0356774081f, 0.0356774081f);
    const __half2 c0 = __floats2half2_rn(0.7978845608f, 0.7978845608f);
    const __half2 hf = __floats2half2_rn(0.5f, 0.5f);
    __half2 x2 = __hmul2(x, x);
    __half2 inner = __hmul2(x, __hfma2(c1, x2, c0));
    uint32_t tu;
    asm("tanh.approx.f16x2 %0, %1;" : "=r"(tu) : "r"(*(uint32_t*)&inner));
    __half2 hx = __hmul2(hf, x);
    __half2 res = __hfma2(hx, *(__half2*)&tu, hx);
    return *(uint32_t*)&res;
}
__device__ __forceinline__ uint32_t f2tf32(float f) {
    uint32_t r;
    asm("cvt.rna.tf32.f32 %0, %1;" : "=r"(r) : "f"(f));
    return r;
}
__device__ __forceinline__ void mma_tf32(float* d, const uint32_t* a, const uint32_t* b) {
    asm volatile("mma.sync.aligned.m16n8k8.row.col.f32.tf32.tf32.f32 "
                 "{%0,%1,%2,%3}, {%4,%5,%6,%7}, {%8,%9}, {%0,%1,%2,%3};"
                 : "+f"(d[0]), "+f"(d[1]), "+f"(d[2]), "+f"(d[3])
                 : "r"(a[0]), "r"(a[1]), "r"(a[2]), "r"(a[3]), "r"(b[0]), "r"(b[1]));
}
__device__ __forceinline__ void mma_fp16(float* d, const uint32_t* a, const uint32_t* b) {
    asm volatile("mma.sync.aligned.m16n8k16.row.col.f32.f16.f16.f32 "
                 "{%0,%1,%2,%3}, {%4,%5,%6,%7}, {%8,%9}, {%0,%1,%2,%3};"
                 : "+f"(d[0]), "+f"(d[1]), "+f"(d[2]), "+f"(d[3])
                 : "r"(a[0]), "r"(a[1]), "r"(a[2]), "r"(a[3]), "r"(b[0]), "r"(b[1]));
}
__device__ __forceinline__ void red4(float* p, float4 v) {
    asm volatile("red.global.add.v4.f32 [%0], {%1,%2,%3,%4};" ::
                 "l"(p), "f"(v.x), "f"(v.y), "f"(v.z), "f"(v.w) : "memory");
}
__device__ __forceinline__ uint32_t pack_h2(float a, float b) {
    __half2 h = __floats2half2_rn(a, b);
    return *(uint32_t*)&h;
}

#define G_STRIDE 68
#define W_STRIDE 72

// ---------------- k_detect: zero deg + dtype detect ----------------
__global__ void __launch_bounds__(256) k_detect(const void* __restrict__ ei) {
    int t = threadIdx.x;
#pragma unroll
    for (int r = 0; r < 32; r++)
        ((int4*)d_deg)[t + 256 * r] = make_int4(0, 0, 0, 0);
    __shared__ int bad;
    if (t == 0) bad = 0;
    __syncthreads();
    if (t < 128) {
        long long v = ((const long long*)ei)[t];
        if (v < 0 || v >= NPTS) atomicOr(&bad, 1);
    }
    __syncthreads();
    if (t == 0) d_is64 = bad ? 0 : 1;
}

// ---------------- k_count ----------------
__global__ void k_count(const void* __restrict__ ei) {
    int e = blockIdx.x * blockDim.x + threadIdx.x;
    if (e < NEDGE) {
        int dd = d_is64 ? (int)((const long long*)ei)[NEDGE + e]
                        : ((const int*)ei)[NEDGE + e];
        atomicAdd(&d_deg[dd], 1);
    }
}

// ---------------- k_scan ----------------
__global__ void __launch_bounds__(1024) k_scan() {
    __shared__ int wsum[32];
    int t = threadIdx.x, lane = t & 31, warp = t >> 5;
    int base = t * 32;
    int v[32];
    int s = 0;
#pragma unroll
    for (int i = 0; i < 32; i++) { v[i] = d_deg[base + i]; s += v[i]; }
    int sc = s;
#pragma unroll
    for (int o = 1; o < 32; o <<= 1) {
        int n = __shfl_up_sync(0xffffffffu, sc, o);
        if (lane >= o) sc += n;
    }
    if (lane == 31) wsum[warp] = sc;
    __syncthreads();
    if (warp == 0) {
        int ws = wsum[lane];
#pragma unroll
        for (int o = 1; o < 32; o <<= 1) {
            int n = __shfl_up_sync(0xffffffffu, ws, o);
            if (lane >= o) ws += n;
        }
        wsum[lane] = ws;
    }
    __syncthreads();
    int off = (warp > 0 ? wsum[warp - 1] : 0) + (sc - s);
#pragma unroll
    for (int i = 0; i < 32; i++) {
        d_cursor[base + i] = off;
        d_invc[base + i] = 1.0f / fmaxf((float)v[i], 1.0f);
        off += v[i];
    }
}

// ---------------- k_sortz: scatter sorted edges + zero agg ----------------
__global__ void __launch_bounds__(256) k_sortz(const void* __restrict__ ei) {
    int e = blockIdx.x * 256 + threadIdx.x;
    int is64 = d_is64;
    int ss, dd;
    if (is64) {
        ss = (int)((const long long*)ei)[e];
        dd = (int)((const long long*)ei)[NEDGE + e];
    } else {
        ss = ((const int*)ei)[e];
        dd = ((const int*)ei)[NEDGE + e];
    }
    int p = atomicAdd(&d_cursor[dd], 1);
    d_ssrc[p] = ss;
    d_sdst[p] = dd;
    ((float4*)d_agg)[e] = make_float4(0.f, 0.f, 0.f, 0.f);
    ((float4*)d_agg)[e + NEDGE] = make_float4(0.f, 0.f, 0.f, 0.f);
}

// ---------------- k_lift: mma tf32, 128 items/block ----------------
#define LIFT_IN   0
#define LIFT_B2   3072
#define LIFT_TS   3328
#define LIFT_WS   (3328 + 34816)
#define LIFT_SMEM (LIFT_WS + 18432)

__global__ void __launch_bounds__(256) k_lift(
    const float* __restrict__ x, const float* __restrict__ pos,
    const float* __restrict__ w1, const float* __restrict__ b1,
    const float* __restrict__ w2, const float* __restrict__ b2)
{
    extern __shared__ char smem[];
    float*    in_s = (float*)(smem + LIFT_IN);
    float*    b2_s = (float*)(smem + LIFT_B2);
    uint32_t* t_s  = (uint32_t*)(smem + LIFT_TS);
    float*    t_sf = (float*)(smem + LIFT_TS);
    uint32_t* w_s  = (uint32_t*)(smem + LIFT_WS);

    int t = threadIdx.x;
    int item0 = blockIdx.x * 128;

    for (int idx = t; idx < 640; idx += 256) {
        int j = idx / 5, i = idx % 5;
        int item = item0 + j;
        int b = item >> 15, n = item & (NPTS - 1);
        in_s[j * 6 + i] = (i < 3) ? x[((size_t)b * NPTS + n) * 3 + i] : pos[n * 2 + (i - 3)];
    }
    if (t < 64) b2_s[t] = b2[t];
    __syncthreads();

    int c  = t & 63, jg = t >> 6;
    int w  = t >> 5, lane = t & 31;
    int r  = lane >> 2, c4 = lane & 3;
    int m0 = w * 16;

    float acc[8][4];
#pragma unroll
    for (int j = 0; j < 8; j++)
        acc[j][0] = acc[j][1] = acc[j][2] = acc[j][3] = 0.f;

    for (int ch = 0; ch < 4; ch++) {
        int cc = ch * 64 + c;
        float w0 = w1[cc], wA = w1[LIFTD + cc], wB = w1[2 * LIFTD + cc];
        float wC = w1[3 * LIFTD + cc], wD = w1[4 * LIFTD + cc];
        float bc = b1[cc];
#pragma unroll 4
        for (int rr = 0; rr < 32; rr++) {
            int row = jg * 32 + rr;
            const float* in = in_s + row * 6;
            float v = bc + in[0] * w0 + in[1] * wA + in[2] * wB + in[3] * wC + in[4] * wD;
            t_s[row * G_STRIDE + c] = f2tf32(gelu_fast(v));
        }
        for (int idx = t; idx < 4096; idx += 256) {
            int k = idx >> 6, n = idx & 63;
            w_s[k * W_STRIDE + n] = f2tf32(w2[(ch * 64 + k) * HID + n]);
        }
        __syncthreads();

#pragma unroll
        for (int kk = 0; kk < 8; kk++) {
            uint32_t a[4];
            a[0] = t_s[(m0 + r)     * G_STRIDE + kk * 8 + c4];
            a[1] = t_s[(m0 + r + 8) * G_STRIDE + kk * 8 + c4];
            a[2] = t_s[(m0 + r)     * G_STRIDE + kk * 8 + c4 + 4];
            a[3] = t_s[(m0 + r + 8) * G_STRIDE + kk * 8 + c4 + 4];
#pragma unroll
            for (int j = 0; j < 8; j++) {
                uint32_t bb[2];
                bb[0] = w_s[(kk * 8 + c4)     * W_STRIDE + j * 8 + r];
                bb[1] = w_s[(kk * 8 + c4 + 4) * W_STRIDE + j * 8 + r];
                mma_tf32(acc[j], a, bb);
            }
        }
        __syncthreads();
    }

#pragma unroll
    for (int j = 0; j < 8; j++) {
        int col = j * 8 + c4 * 2;
        float b0 = b2_s[col], b1v = b2_s[col + 1];
        *(float2*)(t_sf + (m0 + r)     * G_STRIDE + col) = make_float2(acc[j][0] + b0, acc[j][1] + b1v);
        *(float2*)(t_sf + (m0 + r + 8) * G_STRIDE + col) = make_float2(acc[j][2] + b0, acc[j][3] + b1v);
    }
    __syncthreads();
    for (int idx = t; idx < 8192; idx += 256) {
        int row = idx >> 6, cc = idx & 63;
        d_h[(size_t)(item0 + row) * 64 + cc] = t_sf[row * G_STRIDE + cc];
    }
}

// ---------------- k_APd: fused update + mma tf32 + Pd, half2 outputs ------
#define APD_POS  0
#define APD_PW   1024
#define APD_HS   2048
#define APD_WS   (2048 + 34816)
#define APD_SMEM (APD_WS + 18432)

__global__ void __launch_bounds__(256) k_APd(
    const float* __restrict__ pos, const float* __restrict__ kW1_l,
    const float* __restrict__ kb1_l, int do_upd)
{
    extern __shared__ char smem[];
    float*    pos_s = (float*)(smem + APD_POS);
    float*    pw_s  = (float*)(smem + APD_PW);
    uint32_t* h_s   = (uint32_t*)(smem + APD_HS);
    uint32_t* w_s   = (uint32_t*)(smem + APD_WS);

    int t = threadIdx.x;
    int item0 = blockIdx.x * 128;

    if (t < 256) {
        int j = t >> 1, i = t & 1;
        int n = (item0 + j) & (NPTS - 1);
        pos_s[j * 2 + i] = pos[n * 2 + i];
    }
    if (t < 256) pw_s[t] = kW1_l[t];

    if (do_upd) {
        for (int idx = t; idx < 8192; idx += 256) {
            int row = idx >> 6, k = idx & 63;
            size_t gi = (size_t)(item0 + row) * 64 + k;
            float ic = d_invc[(item0 + row) & (NPTS - 1)];
            float v = d_h[gi] + d_agg[gi] * ic;
            d_h[gi] = v;
            d_agg[gi] = 0.f;
            h_s[row * G_STRIDE + k] = f2tf32(v);
        }
    } else {
        for (int idx = t; idx < 8192; idx += 256) {
            int row = idx >> 6, k = idx & 63;
            h_s[row * G_STRIDE + k] = f2tf32(d_h[(size_t)(item0 + row) * 64 + k]);
        }
    }
    for (int idx = t; idx < 4096; idx += 256) {
        int k = idx >> 6, n = idx & 63;
        w_s[k * W_STRIDE + n] = f2tf32(kW1_l[(4 + k) * 64 + n]);
    }
    __syncthreads();

    if (item0 < NPTS) {
        for (int idx = t; idx < 4096; idx += 256) {
            int row = idx >> 5, c2 = idx & 31;
            int n = item0 + row, c = c2 * 2;
            float p0 = pos_s[row * 2], p1 = pos_s[row * 2 + 1];
            float v0 = kb1_l[c]     + p0 * pw_s[128 + c]     + p1 * pw_s[192 + c];
            float v1 = kb1_l[c + 1] + p0 * pw_s[128 + c + 1] + p1 * pw_s[192 + c + 1];
            d_Pdh[(size_t)n * 32 + c2] = pack_h2(v0, v1);
        }
    }

    int w = t >> 5, lane = t & 31;
    int r = lane >> 2, c4 = lane & 3;
    int m0 = w * 16;

    float acc[8][4];
#pragma unroll
    for (int j = 0; j < 8; j++)
        acc[j][0] = acc[j][1] = acc[j][2] = acc[j][3] = 0.f;

#pragma unroll
    for (int kk = 0; kk < 8; kk++) {
        uint32_t a[4];
        a[0] = h_s[(m0 + r)     * G_STRIDE + kk * 8 + c4];
        a[1] = h_s[(m0 + r + 8) * G_STRIDE + kk * 8 + c4];
        a[2] = h_s[(m0 + r)     * G_STRIDE + kk * 8 + c4 + 4];
        a[3] = h_s[(m0 + r + 8) * G_STRIDE + kk * 8 + c4 + 4];
#pragma unroll
        for (int j = 0; j < 8; j++) {
            uint32_t bb[2];
            bb[0] = w_s[(kk * 8 + c4)     * W_STRIDE + j * 8 + r];
            bb[1] = w_s[(kk * 8 + c4 + 4) * W_STRIDE + j * 8 + r];
            mma_tf32(acc[j], a, bb);
        }
    }
    __syncthreads();

    float p00 = pos_s[(m0 + r) * 2],     p01 = pos_s[(m0 + r) * 2 + 1];
    float p10 = pos_s[(m0 + r + 8) * 2], p11 = pos_s[(m0 + r + 8) * 2 + 1];
#pragma unroll
    for (int j = 0; j < 8; j++) {
        int col = j * 8 + c4 * 2;
        float w00 = pw_s[col], w01 = pw_s[col + 1];
        float w10 = pw_s[64 + col], w11 = pw_s[64 + col + 1];
        h_s[(m0 + r) * 36 + j * 4 + c4] =
            pack_h2(acc[j][0] + p00 * w00 + p01 * w10, acc[j][1] + p00 * w01 + p01 * w11);
        h_s[(m0 + r + 8) * 36 + j * 4 + c4] =
            pack_h2(acc[j][2] + p10 * w00 + p11 * w10, acc[j][3] + p10 * w01 + p11 * w11);
    }
    __syncthreads();
    for (int idx = t; idx < 4096; idx += 256) {
        int row = idx >> 5, cc = idx & 31;
        d_Ah[(size_t)(item0 + row) * 32 + cc] = h_s[row * 36 + cc];
    }
}

// ---------------- k_edge: warp-private g/C regions, half2 gelu ------------
// union: 8 warps x 4352B (g 16x36 u32 = 2304B aliased under C 16x68 f32 = 4352B)
#define EU_OFF   0
#define EW_OFF   34816
#define EB_OFF   44032
#define ES_OFF   44288
#define ED_OFF   44800
#define EDGE_SMEM 45312
#define WREG_U32 1088          // 4352 B per warp, bank-aligned (1088 % 32 == 0)
#define GH_STRIDE 36
#define C_STRIDE  68

__global__ void __launch_bounds__(256) k_edge(
    const float* __restrict__ kW2_l, const float* __restrict__ kb2_l)
{
    extern __shared__ char smem[];
    uint32_t* u_s    = (uint32_t*)(smem + EU_OFF);
    uint32_t* w_s    = (uint32_t*)(smem + EW_OFF);
    float*    bias_s = (float*)(smem + EB_OFF);
    int*      src_s  = (int*)(smem + ES_OFF);
    int*      dst_s  = (int*)(smem + ED_OFF);

    int t = threadIdx.x;
    int e_base = blockIdx.x * 128;

    for (int idx = t; idx < 2048; idx += 256) {
        int i = idx >> 6, n = idx & 63;
        w_s[i * W_STRIDE + n] = pack_h2(kW2_l[(2 * i) * 64 + n], kW2_l[(2 * i + 1) * 64 + n]);
    }
    if (t < 128) {
        src_s[t] = d_ssrc[e_base + t];
        dst_s[t] = d_sdst[e_base + t];
    }
    if (t < 64) bias_s[t] = kb2_l[t];

    int w = t >> 5, lane = t & 31;
    int r = lane >> 2, c4 = lane & 3;
    uint32_t* gw = u_s + w * WREG_U32;         // warp-private g (u32, stride 36)
    float*    cw = (float*)gw;                 // warp-private C (f32, stride 68)
    int el = w * 16;                           // this warp's block-local edge base
    int ci4 = (lane & 15) * 4;                 // scatter: column group
    int e0  = (lane >> 4) * 8;                 // scatter: local edge base (0 or 8)
    __syncthreads();   // only block-wide sync: W / bias / indices staged

    for (int b = 0; b < NBATCH; b++) {
        const uint32_t* Ab = d_Ah + (size_t)b * NPTS * 32;

        // phase 1 (warp-local): g[i] = gelu_h2(A[src] + Pd[dst]), lane = channel pair
#pragma unroll 4
        for (int i = 0; i < 16; i++) {
            int ss = src_s[el + i], dd = dst_s[el + i];
            uint32_t pd = d_Pdh[(size_t)dd * 32 + lane];
            uint32_t av = Ab[(size_t)ss * 32 + lane];
            __half2 sum = __hadd2(*(__half2*)&av, *(__half2*)&pd);
            gw[i * GH_STRIDE + lane] = gelu_h2(*(uint32_t*)&sum);
        }
        __syncwarp();

        // phase 2: fp16 mma, 16 edges x 64 cols (warp-local A rows r, r+8)
        float acc[8][4];
#pragma unroll
        for (int j = 0; j < 8; j++) {
            float b0 = bias_s[j * 8 + c4 * 2];
            float b1 = bias_s[j * 8 + c4 * 2 + 1];
            acc[j][0] = b0; acc[j][1] = b1; acc[j][2] = b0; acc[j][3] = b1;
        }
#pragma unroll
        for (int kk = 0; kk < 4; kk++) {
            uint32_t a[4];
            a[0] = gw[r       * GH_STRIDE + kk * 8 + c4];
            a[1] = gw[(r + 8) * GH_STRIDE + kk * 8 + c4];
            a[2] = gw[r       * GH_STRIDE + kk * 8 + c4 + 4];
            a[3] = gw[(r + 8) * GH_STRIDE + kk * 8 + c4 + 4];
#pragma unroll
            for (int j = 0; j < 8; j++) {
                uint32_t bb[2];
                bb[0] = w_s[(kk * 8 + c4)     * W_STRIDE + j * 8 + r];
                bb[1] = w_s[(kk * 8 + c4 + 4) * W_STRIDE + j * 8 + r];
                mma_fp16(acc[j], a, bb);
            }
        }
        __syncwarp();   // warp done reading its g -> safe to overwrite with its C

        // stage C over warp-private region
#pragma unroll
        for (int j = 0; j < 8; j++) {
            *(float2*)(cw + r       * C_STRIDE + j * 8 + c4 * 2) =
                make_float2(acc[j][0], acc[j][1]);
            *(float2*)(cw + (r + 8) * C_STRIDE + j * 8 + c4 * 2) =
                make_float2(acc[j][2], acc[j][3]);
        }
        __syncwarp();

        // run-accumulated scatter (sorted dst), warp-local C rows e0..e0+7
        {
            float* aggb = d_agg + (size_t)b * NPTS * 64;
            int cur = dst_s[el + e0];
            float4 a4 = *(const float4*)(cw + e0 * C_STRIDE + ci4);
#pragma unroll
            for (int i = 1; i < 8; i++) {
                int dd = dst_s[el + e0 + i];
                float4 v = *(const float4*)(cw + (e0 + i) * C_STRIDE + ci4);
                if (dd != cur) {
                    red4(aggb + (size_t)cur * 64 + ci4, a4);
                    a4 = v; cur = dd;
                } else {
                    a4.x += v.x; a4.y += v.y; a4.z += v.z; a4.w += v.w;
                }
            }
            red4(aggb + (size_t)cur * 64 + ci4, a4);
        }
        __syncwarp();   // warp's C region reused as its g next batch
    }
}

// ---------------- k_proj: fused final update + mma tf32 ----------------
#define PROJ_HS   0
#define PROJ_WS   34816
#define PROJ_W2   (34816 + 18432)
#define PROJ_B1   (PROJ_W2 + 1024)
#define PROJ_SMEM (PROJ_B1 + 1024)

__global__ void __launch_bounds__(256) k_proj(
    const float* __restrict__ w1, const float* __restrict__ b1,
    const float* __restrict__ w2, const float* __restrict__ b2,
    float* __restrict__ out)
{
    extern __shared__ char smem[];
    uint32_t* h_s  = (uint32_t*)(smem + PROJ_HS);
    uint32_t* w_s  = (uint32_t*)(smem + PROJ_WS);
    float*    w2_s = (float*)(smem + PROJ_W2);
    float*    b1_s = (float*)(smem + PROJ_B1);

    int t = threadIdx.x;
    int item0 = blockIdx.x * 128;

    for (int idx = t; idx < 8192; idx += 256) {
        int row = idx >> 6, k = idx & 63;
        size_t gi = (size_t)(item0 + row) * 64 + k;
        float ic = d_invc[(item0 + row) & (NPTS - 1)];
        h_s[row * G_STRIDE + k] = f2tf32(d_h[gi] + d_agg[gi] * ic);
    }
    w2_s[t] = w2[t];
    b1_s[t] = b1[t];
    __syncthreads();

    int w = t >> 5, lane = t & 31;
    int r = lane >> 2, c4 = lane & 3;
    int m0 = w * 16;

    uint32_t a[8][4];
#pragma unroll
    for (int kk = 0; kk < 8; kk++) {
        a[kk][0] = h_s[(m0 + r)     * G_STRIDE + kk * 8 + c4];
        a[kk][1] = h_s[(m0 + r + 8) * G_STRIDE + kk * 8 + c4];
        a[kk][2] = h_s[(m0 + r)     * G_STRIDE + kk * 8 + c4 + 4];
        a[kk][3] = h_s[(m0 + r + 8) * G_STRIDE + kk * 8 + c4 + 4];
    }

    float sum0 = 0.f, sum1 = 0.f;
    for (int ch = 0; ch < 4; ch++) {
        __syncthreads();
        for (int idx = t; idx < 4096; idx += 256) {
            int k = idx >> 6, n = idx & 63;
            w_s[k * W_STRIDE + n] = f2tf32(w1[k * 256 + ch * 64 + n]);
        }
        __syncthreads();

        float acc[8][4];
#pragma unroll
        for (int j = 0; j < 8; j++)
            acc[j][0] = acc[j][1] = acc[j][2] = acc[j][3] = 0.f;
#pragma unroll
        for (int kk = 0; kk < 8; kk++) {
#pragma unroll
            for (int j = 0; j < 8; j++) {
                uint32_t bb[2];
                bb[0] = w_s[(kk * 8 + c4)     * W_STRIDE + j * 8 + r];
                bb[1] = w_s[(kk * 8 + c4 + 4) * W_STRIDE + j * 8 + r];
                mma_tf32(acc[j], a[kk], bb);
            }
        }
#pragma unroll
        for (int j = 0; j < 8; j++) {
            int col = ch * 64 + j * 8 + c4 * 2;
            sum0 += gelu_fast(acc[j][0] + b1_s[col]) * w2_s[col]
                  + gelu_fast(acc[j][1] + b1_s[col + 1]) * w2_s[col + 1];
            sum1 += gelu_fast(acc[j][2] + b1_s[col]) * w2_s[col]
                  + gelu_fast(acc[j][3] + b1_s[col + 1]) * w2_s[col + 1];
        }
    }

    sum0 += __shfl_xor_sync(0xffffffffu, sum0, 1);
    sum0 += __shfl_xor_sync(0xffffffffu, sum0, 2);
    sum1 += __shfl_xor_sync(0xffffffffu, sum1, 1);
    sum1 += __shfl_xor_sync(0xffffffffu, sum1, 2);
    if (c4 == 0) {
        float bb = b2[0];
        out[item0 + m0 + r]     = sum0 + bb;
        out[item0 + m0 + r + 8] = sum1 + bb;
    }
}

// ---------------- launch ----------------
extern "C" void kernel_launch(void* const* d_in, const int* in_sizes, int n_in,
                              void* d_out, int out_size) {
    (void)in_sizes; (void)n_in; (void)out_size;
    const float* x    = (const float*)d_in[0];
    const float* pos  = (const float*)d_in[1];
    const void*  ei   = d_in[2];
    const float* lw1  = (const float*)d_in[3];
    const float* lb1  = (const float*)d_in[4];
    const float* lw2  = (const float*)d_in[5];
    const float* lb2  = (const float*)d_in[6];
    const float* kW1  = (const float*)d_in[7];
    const float* kb1  = (const float*)d_in[8];
    const float* kW2  = (const float*)d_in[9];
    const float* kb2  = (const float*)d_in[10];
    const float* pw1  = (const float*)d_in[11];
    const float* pb1  = (const float*)d_in[12];
    const float* pw2  = (const float*)d_in[13];
    const float* pb2  = (const float*)d_in[14];
    float* out = (float*)d_out;

    cudaFuncSetAttribute(k_lift, cudaFuncAttributeMaxDynamicSharedMemorySize, LIFT_SMEM);
    cudaFuncSetAttribute(k_APd,  cudaFuncAttributeMaxDynamicSharedMemorySize, APD_SMEM);
    cudaFuncSetAttribute(k_edge, cudaFuncAttributeMaxDynamicSharedMemorySize, EDGE_SMEM);
    cudaFuncSetAttribute(k_proj, cudaFuncAttributeMaxDynamicSharedMemorySize, PROJ_SMEM);

    k_detect<<<1, 256>>>(ei);                                                       // 0
    k_count<<<NEDGE / 256, 256>>>(ei);                                              // 1
    k_scan<<<1, 1024>>>();                                                          // 2
    k_sortz<<<NEDGE / 256, 256>>>(ei);                                              // 3
    k_lift<<<(NBATCH * NPTS) / 128, 256, LIFT_SMEM>>>(x, pos, lw1, lb1, lw2, lb2);  // 4
    k_APd<<<(NBATCH * NPTS) / 128, 256, APD_SMEM>>>(pos, kW1, kb1, 0);              // 5
    k_edge<<<NEDGE / 128, 256, EDGE_SMEM>>>(kW2, kb2);                              // 6

    for (int l = 1; l < NLAYER; l++) {
        const float* W1l = kW1 + (size_t)l * 68 * 64;
        const float* b1l = kb1 + (size_t)l * 64;
        const float* W2l = kW2 + (size_t)l * 64 * 64;
        const float* b2l = kb2 + (size_t)l * 64;
        k_APd<<<(NBATCH * NPTS) / 128, 256, APD_SMEM>>>(pos, W1l, b1l, 1);
        k_edge<<<NEDGE / 128, 256, EDGE_SMEM>>>(W2l, b2l);
    }

    k_proj<<<(NBATCH * NPTS) / 128, 256, PROJ_SMEM>>>(pw1, pb1, pw2, pb2, out);
}

// round 12
// speedup vs baseline: 1.2872x; 1.2872x over previous
#include <cuda_runtime.h>
#include <cuda_fp16.h>
#include <math.h>
#include <stdint.h>

#define NPTS   32768
#define NEDGE  524288
#define NBATCH 2
#define HID    64
#define LIFTD  256
#define NLAYER 4

// ---------------- scratch ----------------
__device__ float    d_h[NBATCH * NPTS * HID];
__device__ uint32_t d_Ah[NBATCH * NPTS * 32];   // half2-packed A
__device__ uint32_t d_Pdh[NPTS * 32];           // half2-packed Pd
__device__ float    d_agg[NBATCH * NPTS * HID]; // now: G = sum of gelu (pre-W2)
__device__ float    d_invc[NPTS];
__device__ int      d_deg[NPTS];
__device__ int      d_cursor[NPTS];
__device__ int      d_ssrc[NEDGE];
__device__ int      d_sdst[NEDGE];
__device__ int      d_is64;

// fast tanh-form gelu (fp32)
__device__ __forceinline__ float gelu_fast(float x) {
    float x2 = x * x;
    float inner = x * fmaf(0.0356774081f, x2, 0.7978845608f);
    float t;
    asm("tanh.approx.f32 %0, %1;" : "=f"(t) : "f"(inner));
    float hx = 0.5f * x;
    return fmaf(hx, t, hx);
}
// packed half2 tanh-form gelu
__device__ __forceinline__ uint32_t gelu_h2(uint32_t xu) {
    __half2 x = *(__half2*)&xu;
    const __half2 c1 = __floats2half2_rn(0.0356774081f, 0.0356774081f);
    const __half2 c0 = __floats2half2_rn(0.7978845608f, 0.7978845608f);
    const __half2 hf = __floats2half2_rn(0.5f, 0.5f);
    __half2 x2 = __hmul2(x, x);
    __half2 inner = __hmul2(x, __hfma2(c1, x2, c0));
    uint32_t tu;
    asm("tanh.approx.f16x2 %0, %1;" : "=r"(tu) : "r"(*(uint32_t*)&inner));
    __half2 hx = __hmul2(hf, x);
    __half2 res = __hfma2(hx, *(__half2*)&tu, hx);
    return *(uint32_t*)&res;
}
__device__ __forceinline__ uint32_t f2tf32(float f) {
    uint32_t r;
    asm("cvt.rna.tf32.f32 %0, %1;" : "=r"(r) : "f"(f));
    return r;
}
__device__ __forceinline__ void mma_tf32(float* d, const uint32_t* a, const uint32_t* b) {
    asm volatile("mma.sync.aligned.m16n8k8.row.col.f32.tf32.tf32.f32 "
                 "{%0,%1,%2,%3}, {%4,%5,%6,%7}, {%8,%9}, {%0,%1,%2,%3};"
                 : "+f"(d[0]), "+f"(d[1]), "+f"(d[2]), "+f"(d[3])
                 : "r"(a[0]), "r"(a[1]), "r"(a[2]), "r"(a[3]), "r"(b[0]), "r"(b[1]));
}
__device__ __forceinline__ void red2(float* p, float a, float b) {
    asm volatile("red.global.add.v2.f32 [%0], {%1,%2};" :: "l"(p), "f"(a), "f"(b) : "memory");
}
__device__ __forceinline__ uint32_t pack_h2(float a, float b) {
    __half2 h = __floats2half2_rn(a, b);
    return *(uint32_t*)&h;
}
__device__ __forceinline__ float2 unpack_h2(uint32_t u) {
    return __half22float2(*(__half2*)&u);
}

#define G_STRIDE 68
#define W_STRIDE 72

// ---------------- k_detect ----------------
__global__ void __launch_bounds__(256) k_detect(const void* __restrict__ ei) {
    int t = threadIdx.x;
#pragma unroll
    for (int r = 0; r < 32; r++)
        ((int4*)d_deg)[t + 256 * r] = make_int4(0, 0, 0, 0);
    __shared__ int bad;
    if (t == 0) bad = 0;
    __syncthreads();
    if (t < 128) {
        long long v = ((const long long*)ei)[t];
        if (v < 0 || v >= NPTS) atomicOr(&bad, 1);
    }
    __syncthreads();
    if (t == 0) d_is64 = bad ? 0 : 1;
}

// ---------------- k_count ----------------
__global__ void k_count(const void* __restrict__ ei) {
    int e = blockIdx.x * blockDim.x + threadIdx.x;
    if (e < NEDGE) {
        int dd = d_is64 ? (int)((const long long*)ei)[NEDGE + e]
                        : ((const int*)ei)[NEDGE + e];
        atomicAdd(&d_deg[dd], 1);
    }
}

// ---------------- k_scan ----------------
__global__ void __launch_bounds__(1024) k_scan() {
    __shared__ int wsum[32];
    int t = threadIdx.x, lane = t & 31, warp = t >> 5;
    int base = t * 32;
    int v[32];
    int s = 0;
#pragma unroll
    for (int i = 0; i < 32; i++) { v[i] = d_deg[base + i]; s += v[i]; }
    int sc = s;
#pragma unroll
    for (int o = 1; o < 32; o <<= 1) {
        int n = __shfl_up_sync(0xffffffffu, sc, o);
        if (lane >= o) sc += n;
    }
    if (lane == 31) wsum[warp] = sc;
    __syncthreads();
    if (warp == 0) {
        int ws = wsum[lane];
#pragma unroll
        for (int o = 1; o < 32; o <<= 1) {
            int n = __shfl_up_sync(0xffffffffu, ws, o);
            if (lane >= o) ws += n;
        }
        wsum[lane] = ws;
    }
    __syncthreads();
    int off = (warp > 0 ? wsum[warp - 1] : 0) + (sc - s);
#pragma unroll
    for (int i = 0; i < 32; i++) {
        d_cursor[base + i] = off;
        d_invc[base + i] = 1.0f / fmaxf((float)v[i], 1.0f);
        off += v[i];
    }
}

// ---------------- k_sortz: sorted edges + zero agg ----------------
__global__ void __launch_bounds__(256) k_sortz(const void* __restrict__ ei) {
    int e = blockIdx.x * 256 + threadIdx.x;
    int is64 = d_is64;
    int ss, dd;
    if (is64) {
        ss = (int)((const long long*)ei)[e];
        dd = (int)((const long long*)ei)[NEDGE + e];
    } else {
        ss = ((const int*)ei)[e];
        dd = ((const int*)ei)[NEDGE + e];
    }
    int p = atomicAdd(&d_cursor[dd], 1);
    d_ssrc[p] = ss;
    d_sdst[p] = dd;
    ((float4*)d_agg)[e] = make_float4(0.f, 0.f, 0.f, 0.f);
    ((float4*)d_agg)[e + NEDGE] = make_float4(0.f, 0.f, 0.f, 0.f);
}

// ---------------- k_lift (unchanged) ----------------
#define LIFT_IN   0
#define LIFT_B2   3072
#define LIFT_TS   3328
#define LIFT_WS   (3328 + 34816)
#define LIFT_SMEM (LIFT_WS + 18432)

__global__ void __launch_bounds__(256) k_lift(
    const float* __restrict__ x, const float* __restrict__ pos,
    const float* __restrict__ w1, const float* __restrict__ b1,
    const float* __restrict__ w2, const float* __restrict__ b2)
{
    extern __shared__ char smem[];
    float*    in_s = (float*)(smem + LIFT_IN);
    float*    b2_s = (float*)(smem + LIFT_B2);
    uint32_t* t_s  = (uint32_t*)(smem + LIFT_TS);
    float*    t_sf = (float*)(smem + LIFT_TS);
    uint32_t* w_s  = (uint32_t*)(smem + LIFT_WS);

    int t = threadIdx.x;
    int item0 = blockIdx.x * 128;

    for (int idx = t; idx < 640; idx += 256) {
        int j = idx / 5, i = idx % 5;
        int item = item0 + j;
        int b = item >> 15, n = item & (NPTS - 1);
        in_s[j * 6 + i] = (i < 3) ? x[((size_t)b * NPTS + n) * 3 + i] : pos[n * 2 + (i - 3)];
    }
    if (t < 64) b2_s[t] = b2[t];
    __syncthreads();

    int c  = t & 63, jg = t >> 6;
    int w  = t >> 5, lane = t & 31;
    int r  = lane >> 2, c4 = lane & 3;
    int m0 = w * 16;

    float acc[8][4];
#pragma unroll
    for (int j = 0; j < 8; j++)
        acc[j][0] = acc[j][1] = acc[j][2] = acc[j][3] = 0.f;

    for (int ch = 0; ch < 4; ch++) {
        int cc = ch * 64 + c;
        float w0 = w1[cc], wA = w1[LIFTD + cc], wB = w1[2 * LIFTD + cc];
        float wC = w1[3 * LIFTD + cc], wD = w1[4 * LIFTD + cc];
        float bc = b1[cc];
#pragma unroll 4
        for (int rr = 0; rr < 32; rr++) {
            int row = jg * 32 + rr;
            const float* in = in_s + row * 6;
            float v = bc + in[0] * w0 + in[1] * wA + in[2] * wB + in[3] * wC + in[4] * wD;
            t_s[row * G_STRIDE + c] = f2tf32(gelu_fast(v));
        }
        for (int idx = t; idx < 4096; idx += 256) {
            int k = idx >> 6, n = idx & 63;
            w_s[k * W_STRIDE + n] = f2tf32(w2[(ch * 64 + k) * HID + n]);
        }
        __syncthreads();

#pragma unroll
        for (int kk = 0; kk < 8; kk++) {
            uint32_t a[4];
            a[0] = t_s[(m0 + r)     * G_STRIDE + kk * 8 + c4];
            a[1] = t_s[(m0 + r + 8) * G_STRIDE + kk * 8 + c4];
            a[2] = t_s[(m0 + r)     * G_STRIDE + kk * 8 + c4 + 4];
            a[3] = t_s[(m0 + r + 8) * G_STRIDE + kk * 8 + c4 + 4];
#pragma unroll
            for (int j = 0; j < 8; j++) {
                uint32_t bb[2];
                bb[0] = w_s[(kk * 8 + c4)     * W_STRIDE + j * 8 + r];
                bb[1] = w_s[(kk * 8 + c4 + 4) * W_STRIDE + j * 8 + r];
                mma_tf32(acc[j], a, bb);
            }
        }
        __syncthreads();
    }

#pragma unroll
    for (int j = 0; j < 8; j++) {
        int col = j * 8 + c4 * 2;
        float b0 = b2_s[col], b1v = b2_s[col + 1];
        *(float2*)(t_sf + (m0 + r)     * G_STRIDE + col) = make_float2(acc[j][0] + b0, acc[j][1] + b1v);
        *(float2*)(t_sf + (m0 + r + 8) * G_STRIDE + col) = make_float2(acc[j][2] + b0, acc[j][3] + b1v);
    }
    __syncthreads();
    for (int idx = t; idx < 8192; idx += 256) {
        int row = idx >> 6, cc = idx & 63;
        d_h[(size_t)(item0 + row) * 64 + cc] = t_sf[row * G_STRIDE + cc];
    }
}

// ---------------- k_APd: fused (G@W2 update) + Pd + (h@W1 -> A) ----------
#define APD_POS  0
#define APD_PW   1024
#define APD_KB2  2048
#define APD_HS   2304
#define APD_WS   (2304 + 34816)
#define APD_SMEM (APD_WS + 18432)

__global__ void __launch_bounds__(256) k_APd(
    const float* __restrict__ pos, const float* __restrict__ kW1_l,
    const float* __restrict__ kb1_l, const float* __restrict__ kW2_p,
    const float* __restrict__ kb2_p, int do_upd)
{
    extern __shared__ char smem[];
    float*    pos_s  = (float*)(smem + APD_POS);
    float*    pw_s   = (float*)(smem + APD_PW);
    float*    kb2_s  = (float*)(smem + APD_KB2);
    uint32_t* h_s    = (uint32_t*)(smem + APD_HS);
    uint32_t* w_s    = (uint32_t*)(smem + APD_WS);

    int t = threadIdx.x;
    int item0 = blockIdx.x * 128;
    int w = t >> 5, lane = t & 31;
    int r = lane >> 2, c4 = lane & 3;
    int m0 = w * 16;

    if (t < 256) {
        int j = t >> 1, i = t & 1;
        int n = (item0 + j) & (NPTS - 1);
        pos_s[j * 2 + i] = pos[n * 2 + i];
    }
    if (t < 256) pw_s[t] = kW1_l[t];
    if (do_upd && t < 64) kb2_s[t] = kb2_p[t];

    if (do_upd) {
        // stage G (warp-local rows) as tf32; zero agg
#pragma unroll 4
        for (int i = 0; i < 16; i++) {
            int row = m0 + i;
            size_t gi = (size_t)(item0 + row) * 64;
            float g0 = d_agg[gi + lane], g1 = d_agg[gi + 32 + lane];
            d_agg[gi + lane] = 0.f;
            d_agg[gi + 32 + lane] = 0.f;
            h_s[row * G_STRIDE + lane] = f2tf32(g0);
            h_s[row * G_STRIDE + 32 + lane] = f2tf32(g1);
        }
        // stage W2_prev (block-wide)
        for (int idx = t; idx < 4096; idx += 256) {
            int k = idx >> 6, n = idx & 63;
            w_s[k * W_STRIDE + n] = f2tf32(kW2_p[k * 64 + n]);
        }
        __syncthreads();

        // MMA1: G @ W2
        float acc[8][4];
#pragma unroll
        for (int j = 0; j < 8; j++)
            acc[j][0] = acc[j][1] = acc[j][2] = acc[j][3] = 0.f;
#pragma unroll
        for (int kk = 0; kk < 8; kk++) {
            uint32_t a[4];
            a[0] = h_s[(m0 + r)     * G_STRIDE + kk * 8 + c4];
            a[1] = h_s[(m0 + r + 8) * G_STRIDE + kk * 8 + c4];
            a[2] = h_s[(m0 + r)     * G_STRIDE + kk * 8 + c4 + 4];
            a[3] = h_s[(m0 + r + 8) * G_STRIDE + kk * 8 + c4 + 4];
#pragma unroll
            for (int j = 0; j < 8; j++) {
                uint32_t bb[2];
                bb[0] = w_s[(kk * 8 + c4)     * W_STRIDE + j * 8 + r];
                bb[1] = w_s[(kk * 8 + c4 + 4) * W_STRIDE + j * 8 + r];
                mma_tf32(acc[j], a, bb);
            }
        }
        __syncwarp();

        // h_new = h + (acc + deg*kb2) * invc; write d_h; restage tf32 into h_s
        int nA = (item0 + m0 + r) & (NPTS - 1);
        int nB = (item0 + m0 + r + 8) & (NPTS - 1);
        float iA = d_invc[nA], dA = (float)d_deg[nA];
        float iB = d_invc[nB], dB = (float)d_deg[nB];
        size_t gA = (size_t)(item0 + m0 + r) * 64;
        size_t gB = (size_t)(item0 + m0 + r + 8) * 64;
#pragma unroll
        for (int j = 0; j < 8; j++) {
            int col = j * 8 + c4 * 2;
            float k0 = kb2_s[col], k1 = kb2_s[col + 1];
            float2 hA = *(float2*)(d_h + gA + col);
            float2 hB = *(float2*)(d_h + gB + col);
            float a0 = hA.x + (acc[j][0] + dA * k0) * iA;
            float a1 = hA.y + (acc[j][1] + dA * k1) * iA;
            float b0 = hB.x + (acc[j][2] + dB * k0) * iB;
            float b1 = hB.y + (acc[j][3] + dB * k1) * iB;
            *(float2*)(d_h + gA + col) = make_float2(a0, a1);
            *(float2*)(d_h + gB + col) = make_float2(b0, b1);
            h_s[(m0 + r) * G_STRIDE + col]     = f2tf32(a0);
            h_s[(m0 + r) * G_STRIDE + col + 1] = f2tf32(a1);
            h_s[(m0 + r + 8) * G_STRIDE + col]     = f2tf32(b0);
            h_s[(m0 + r + 8) * G_STRIDE + col + 1] = f2tf32(b1);
        }
        __syncthreads();   // all warps done with W2 region
    } else {
        for (int idx = t; idx < 8192; idx += 256) {
            int row = idx >> 6, k = idx & 63;
            h_s[row * G_STRIDE + k] = f2tf32(d_h[(size_t)(item0 + row) * 64 + k]);
        }
    }

    // stage W1[4:68]
    for (int idx = t; idx < 4096; idx += 256) {
        int k = idx >> 6, n = idx & 63;
        w_s[k * W_STRIDE + n] = f2tf32(kW1_l[(4 + k) * 64 + n]);
    }
    __syncthreads();

    // Pd (current layer), b0 blocks cover all n
    if (item0 < NPTS) {
        for (int idx = t; idx < 4096; idx += 256) {
            int row = idx >> 5, c2 = idx & 31;
            int n = item0 + row, c = c2 * 2;
            float p0 = pos_s[row * 2], p1 = pos_s[row * 2 + 1];
            float v0 = kb1_l[c]     + p0 * pw_s[128 + c]     + p1 * pw_s[192 + c];
            float v1 = kb1_l[c + 1] + p0 * pw_s[128 + c + 1] + p1 * pw_s[192 + c + 1];
            d_Pdh[(size_t)n * 32 + c2] = pack_h2(v0, v1);
        }
    }

    // MMA2: h @ W1[4:68] -> A
    float acc[8][4];
#pragma unroll
    for (int j = 0; j < 8; j++)
        acc[j][0] = acc[j][1] = acc[j][2] = acc[j][3] = 0.f;
#pragma unroll
    for (int kk = 0; kk < 8; kk++) {
        uint32_t a[4];
        a[0] = h_s[(m0 + r)     * G_STRIDE + kk * 8 + c4];
        a[1] = h_s[(m0 + r + 8) * G_STRIDE + kk * 8 + c4];
        a[2] = h_s[(m0 + r)     * G_STRIDE + kk * 8 + c4 + 4];
        a[3] = h_s[(m0 + r + 8) * G_STRIDE + kk * 8 + c4 + 4];
#pragma unroll
        for (int j = 0; j < 8; j++) {
            uint32_t bb[2];
            bb[0] = w_s[(kk * 8 + c4)     * W_STRIDE + j * 8 + r];
            bb[1] = w_s[(kk * 8 + c4 + 4) * W_STRIDE + j * 8 + r];
            mma_tf32(acc[j], a, bb);
        }
    }
    __syncthreads();

    float p00 = pos_s[(m0 + r) * 2],     p01 = pos_s[(m0 + r) * 2 + 1];
    float p10 = pos_s[(m0 + r + 8) * 2], p11 = pos_s[(m0 + r + 8) * 2 + 1];
#pragma unroll
    for (int j = 0; j < 8; j++) {
        int col = j * 8 + c4 * 2;
        float w00 = pw_s[col], w01 = pw_s[col + 1];
        float w10 = pw_s[64 + col], w11 = pw_s[64 + col + 1];
        h_s[(m0 + r) * 36 + j * 4 + c4] =
            pack_h2(acc[j][0] + p00 * w00 + p01 * w10, acc[j][1] + p00 * w01 + p01 * w11);
        h_s[(m0 + r + 8) * 36 + j * 4 + c4] =
            pack_h2(acc[j][2] + p10 * w00 + p11 * w10, acc[j][3] + p10 * w01 + p11 * w11);
    }
    __syncthreads();
    for (int idx = t; idx < 4096; idx += 256) {
        int row = idx >> 5, cc = idx & 31;
        d_Ah[(size_t)(item0 + row) * 32 + cc] = h_s[row * 36 + cc];
    }
}

// ---------------- k_edge: pure gather+gelu+scatter (no MMA) ---------------
// 512 edges/block, 64 edges/warp, lane = channel pair. smem = indices only.
__global__ void __launch_bounds__(256) k_edge()
{
    __shared__ int src_s[512];
    __shared__ int dst_s[512];

    int t = threadIdx.x;
    int e_base = blockIdx.x * 512;
    src_s[t]       = d_ssrc[e_base + t];
    src_s[t + 256] = d_ssrc[e_base + 256 + t];
    dst_s[t]       = d_sdst[e_base + t];
    dst_s[t + 256] = d_sdst[e_base + 256 + t];
    __syncthreads();

    int w = t >> 5, lane = t & 31;
    int eb = w * 64;

#pragma unroll
    for (int b = 0; b < NBATCH; b++) {
        const uint32_t* Ab = d_Ah + (size_t)b * NPTS * 32;
        float* aggb = d_agg + (size_t)b * NPTS * 64;

        int   cur = dst_s[eb];
        float a0 = 0.f, a1 = 0.f;
#pragma unroll 4
        for (int e = 0; e < 64; e++) {
            int ss = src_s[eb + e], dd = dst_s[eb + e];
            uint32_t av = Ab[(size_t)ss * 32 + lane];
            uint32_t pd = d_Pdh[(size_t)dd * 32 + lane];
            __half2 sum = __hadd2(*(__half2*)&av, *(__half2*)&pd);
            float2 f = unpack_h2(gelu_h2(*(uint32_t*)&sum));
            if (dd != cur) {
                red2(aggb + (size_t)cur * 64 + lane * 2, a0, a1);
                cur = dd; a0 = f.x; a1 = f.y;
            } else {
                a0 += f.x; a1 += f.y;
            }
        }
        red2(aggb + (size_t)cur * 64 + lane * 2, a0, a1);
    }
}

// ---------------- k_proj: fused (G@W2 update) + proj MLP ------------------
#define PROJ_HS   0
#define PROJ_WS   34816
#define PROJ_W2   (34816 + 18432)
#define PROJ_B1   (PROJ_W2 + 1024)
#define PROJ_KB2  (PROJ_B1 + 1024)
#define PROJ_SMEM (PROJ_KB2 + 256)

__global__ void __launch_bounds__(256) k_proj(
    const float* __restrict__ w1, const float* __restrict__ b1,
    const float* __restrict__ w2, const float* __restrict__ b2,
    const float* __restrict__ kW2_p, const float* __restrict__ kb2_p,
    float* __restrict__ out)
{
    extern __shared__ char smem[];
    uint32_t* h_s   = (uint32_t*)(smem + PROJ_HS);
    uint32_t* w_s   = (uint32_t*)(smem + PROJ_WS);
    float*    w2_s  = (float*)(smem + PROJ_W2);
    float*    b1_s  = (float*)(smem + PROJ_B1);
    float*    kb2_s = (float*)(smem + PROJ_KB2);

    int t = threadIdx.x;
    int item0 = blockIdx.x * 128;
    int w = t >> 5, lane = t & 31;
    int r = lane >> 2, c4 = lane & 3;
    int m0 = w * 16;

    w2_s[t] = w2[t];
    b1_s[t] = b1[t];
    if (t < 64) kb2_s[t] = kb2_p[t];

    // stage G (warp-local rows) as tf32
#pragma unroll 4
    for (int i = 0; i < 16; i++) {
        int row = m0 + i;
        size_t gi = (size_t)(item0 + row) * 64;
        h_s[row * G_STRIDE + lane]      = f2tf32(d_agg[gi + lane]);
        h_s[row * G_STRIDE + 32 + lane] = f2tf32(d_agg[gi + 32 + lane]);
    }
    // stage W2_prev
    for (int idx = t; idx < 4096; idx += 256) {
        int k = idx >> 6, n = idx & 63;
        w_s[k * W_STRIDE + n] = f2tf32(kW2_p[k * 64 + n]);
    }
    __syncthreads();

    // MMA1: G @ W2
    {
        float acc[8][4];
#pragma unroll
        for (int j = 0; j < 8; j++)
            acc[j][0] = acc[j][1] = acc[j][2] = acc[j][3] = 0.f;
#pragma unroll
        for (int kk = 0; kk < 8; kk++) {
            uint32_t a[4];
            a[0] = h_s[(m0 + r)     * G_STRIDE + kk * 8 + c4];
            a[1] = h_s[(m0 + r + 8) * G_STRIDE + kk * 8 + c4];
            a[2] = h_s[(m0 + r)     * G_STRIDE + kk * 8 + c4 + 4];
            a[3] = h_s[(m0 + r + 8) * G_STRIDE + kk * 8 + c4 + 4];
#pragma unroll
            for (int j = 0; j < 8; j++) {
                uint32_t bb[2];
                bb[0] = w_s[(kk * 8 + c4)     * W_STRIDE + j * 8 + r];
                bb[1] = w_s[(kk * 8 + c4 + 4) * W_STRIDE + j * 8 + r];
                mma_tf32(acc[j], a, bb);
            }
        }
        __syncwarp();

        int nA = (item0 + m0 + r) & (NPTS - 1);
        int nB = (item0 + m0 + r + 8) & (NPTS - 1);
        float iA = d_invc[nA], dA = (float)d_deg[nA];
        float iB = d_invc[nB], dB = (float)d_deg[nB];
        size_t gA = (size_t)(item0 + m0 + r) * 64;
        size_t gB = (size_t)(item0 + m0 + r + 8) * 64;
#pragma unroll
        for (int j = 0; j < 8; j++) {
            int col = j * 8 + c4 * 2;
            float k0 = kb2_s[col], k1 = kb2_s[col + 1];
            float2 hA = *(float2*)(d_h + gA + col);
            float2 hB = *(float2*)(d_h + gB + col);
            h_s[(m0 + r) * G_STRIDE + col]     = f2tf32(hA.x + (acc[j][0] + dA * k0) * iA);
            h_s[(m0 + r) * G_STRIDE + col + 1] = f2tf32(hA.y + (acc[j][1] + dA * k1) * iA);
            h_s[(m0 + r + 8) * G_STRIDE + col]     = f2tf32(hB.x + (acc[j][2] + dB * k0) * iB);
            h_s[(m0 + r + 8) * G_STRIDE + col + 1] = f2tf32(hB.y + (acc[j][3] + dB * k1) * iB);
        }
        __syncwarp();
    }

    uint32_t a[8][4];
#pragma unroll
    for (int kk = 0; kk < 8; kk++) {
        a[kk][0] = h_s[(m0 + r)     * G_STRIDE + kk * 8 + c4];
        a[kk][1] = h_s[(m0 + r + 8) * G_STRIDE + kk * 8 + c4];
        a[kk][2] = h_s[(m0 + r)     * G_STRIDE + kk * 8 + c4 + 4];
        a[kk][3] = h_s[(m0 + r + 8) * G_STRIDE + kk * 8 + c4 + 4];
    }

    float sum0 = 0.f, sum1 = 0.f;
    for (int ch = 0; ch < 4; ch++) {
        __syncthreads();
        for (int idx = t; idx < 4096; idx += 256) {
            int k = idx >> 6, n = idx & 63;
            w_s[k * W_STRIDE + n] = f2tf32(w1[k * 256 + ch * 64 + n]);
        }
        __syncthreads();

        float acc[8][4];
#pragma unroll
        for (int j = 0; j < 8; j++)
            acc[j][0] = acc[j][1] = acc[j][2] = acc[j][3] = 0.f;
#pragma unroll
        for (int kk = 0; kk < 8; kk++) {
#pragma unroll
            for (int j = 0; j < 8; j++) {
                uint32_t bb[2];
                bb[0] = w_s[(kk * 8 + c4)     * W_STRIDE + j * 8 + r];
                bb[1] = w_s[(kk * 8 + c4 + 4) * W_STRIDE + j * 8 + r];
                mma_tf32(acc[j], a[kk], bb);
            }
        }
#pragma unroll
        for (int j = 0; j < 8; j++) {
            int col = ch * 64 + j * 8 + c4 * 2;
            sum0 += gelu_fast(acc[j][0] + b1_s[col]) * w2_s[col]
                  + gelu_fast(acc[j][1] + b1_s[col + 1]) * w2_s[col + 1];
            sum1 += gelu_fast(acc[j][2] + b1_s[col]) * w2_s[col]
                  + gelu_fast(acc[j][3] + b1_s[col + 1]) * w2_s[col + 1];
        }
    }

    sum0 += __shfl_xor_sync(0xffffffffu, sum0, 1);
    sum0 += __shfl_xor_sync(0xffffffffu, sum0, 2);
    sum1 += __shfl_xor_sync(0xffffffffu, sum1, 1);
    sum1 += __shfl_xor_sync(0xffffffffu, sum1, 2);
    if (c4 == 0) {
        float bb = b2[0];
        out[item0 + m0 + r]     = sum0 + bb;
        out[item0 + m0 + r + 8] = sum1 + bb;
    }
}

// ---------------- launch ----------------
extern "C" void kernel_launch(void* const* d_in, const int* in_sizes, int n_in,
                              void* d_out, int out_size) {
    (void)in_sizes; (void)n_in; (void)out_size;
    const float* x    = (const float*)d_in[0];
    const float* pos  = (const float*)d_in[1];
    const void*  ei   = d_in[2];
    const float* lw1  = (const float*)d_in[3];
    const float* lb1  = (const float*)d_in[4];
    const float* lw2  = (const float*)d_in[5];
    const float* lb2  = (const float*)d_in[6];
    const float* kW1  = (const float*)d_in[7];
    const float* kb1  = (const float*)d_in[8];
    const float* kW2  = (const float*)d_in[9];
    const float* kb2  = (const float*)d_in[10];
    const float* pw1  = (const float*)d_in[11];
    const float* pb1  = (const float*)d_in[12];
    const float* pw2  = (const float*)d_in[13];
    const float* pb2  = (const float*)d_in[14];
    float* out = (float*)d_out;

    cudaFuncSetAttribute(k_lift, cudaFuncAttributeMaxDynamicSharedMemorySize, LIFT_SMEM);
    cudaFuncSetAttribute(k_APd,  cudaFuncAttributeMaxDynamicSharedMemorySize, APD_SMEM);
    cudaFuncSetAttribute(k_proj, cudaFuncAttributeMaxDynamicSharedMemorySize, PROJ_SMEM);

    k_detect<<<1, 256>>>(ei);
    k_count<<<NEDGE / 256, 256>>>(ei);
    k_scan<<<1, 1024>>>();
    k_sortz<<<NEDGE / 256, 256>>>(ei);
    k_lift<<<(NBATCH * NPTS) / 128, 256, LIFT_SMEM>>>(x, pos, lw1, lb1, lw2, lb2);

    for (int l = 0; l < NLAYER; l++) {
        const float* W1l = kW1 + (size_t)l * 68 * 64;
        const float* b1l = kb1 + (size_t)l * 64;
        const float* W2p = kW2 + (size_t)(l - 1) * 64 * 64;   // unused when l==0
        const float* b2p = kb2 + (size_t)(l - 1) * 64;
        k_APd<<<(NBATCH * NPTS) / 128, 256, APD_SMEM>>>(
            pos, W1l, b1l, l > 0 ? W2p : kW2, l > 0 ? b2p : kb2, l > 0);
        k_edge<<<NEDGE / 512, 256>>>();
    }

    k_proj<<<(NBATCH * NPTS) / 128, 256, PROJ_SMEM>>>(
        pw1, pb1, pw2, pb2,
        kW2 + (size_t)(NLAYER - 1) * 64 * 64, kb2 + (size_t)(NLAYER - 1) * 64, out);
}

// round 13
// speedup vs baseline: 1.3966x; 1.0850x over previous
#include <cuda_runtime.h>
#include <cuda_fp16.h>
#include <math.h>
#include <stdint.h>

#define NPTS   32768
#define NEDGE  524288
#define NBATCH 2
#define HID    64
#define LIFTD  256
#define NLAYER 4

// ---------------- scratch ----------------
__device__ float    d_h[NBATCH * NPTS * HID];
__device__ uint32_t d_Ah[NBATCH * NPTS * 32];   // half2-packed A
__device__ uint32_t d_Pdh[NPTS * 32];           // half2-packed Pd
__device__ float    d_agg[NBATCH * NPTS * HID]; // G = sum of gelu (pre-W2)
__device__ float    d_invc[NPTS];
__device__ int      d_deg[NPTS];
__device__ int      d_cursor[NPTS];
__device__ int      d_ssrc[NEDGE];
__device__ int      d_sdst[NEDGE];
__device__ int      d_is64;

// fast tanh-form gelu (fp32)
__device__ __forceinline__ float gelu_fast(float x) {
    float x2 = x * x;
    float inner = x * fmaf(0.0356774081f, x2, 0.7978845608f);
    float t;
    asm("tanh.approx.f32 %0, %1;" : "=f"(t) : "f"(inner));
    float hx = 0.5f * x;
    return fmaf(hx, t, hx);
}
// packed half2 tanh-form gelu
__device__ __forceinline__ uint32_t gelu_h2(uint32_t xu) {
    __half2 x = *(__half2*)&xu;
    const __half2 c1 = __floats2half2_rn(0.0356774081f, 0.0356774081f);
    const __half2 c0 = __floats2half2_rn(0.7978845608f, 0.7978845608f);
    const __half2 hf = __floats2half2_rn(0.5f, 0.5f);
    __half2 x2 = __hmul2(x, x);
    __half2 inner = __hmul2(x, __hfma2(c1, x2, c0));
    uint32_t tu;
    asm("tanh.approx.f16x2 %0, %1;" : "=r"(tu) : "r"(*(uint32_t*)&inner));
    __half2 hx = __hmul2(hf, x);
    __half2 res = __hfma2(hx, *(__half2*)&tu, hx);
    return *(uint32_t*)&res;
}
__device__ __forceinline__ uint32_t f2tf32(float f) {
    uint32_t r;
    asm("cvt.rna.tf32.f32 %0, %1;" : "=r"(r) : "f"(f));
    return r;
}
__device__ __forceinline__ void mma_tf32(float* d, const uint32_t* a, const uint32_t* b) {
    asm volatile("mma.sync.aligned.m16n8k8.row.col.f32.tf32.tf32.f32 "
                 "{%0,%1,%2,%3}, {%4,%5,%6,%7}, {%8,%9}, {%0,%1,%2,%3};"
                 : "+f"(d[0]), "+f"(d[1]), "+f"(d[2]), "+f"(d[3])
                 : "r"(a[0]), "r"(a[1]), "r"(a[2]), "r"(a[3]), "r"(b[0]), "r"(b[1]));
}
__device__ __forceinline__ void red2(float* p, float a, float b) {
    asm volatile("red.global.add.v2.f32 [%0], {%1,%2};" :: "l"(p), "f"(a), "f"(b) : "memory");
}
__device__ __forceinline__ uint32_t pack_h2(float a, float b) {
    __half2 h = __floats2half2_rn(a, b);
    return *(uint32_t*)&h;
}
__device__ __forceinline__ float2 unpack_h2(uint32_t u) {
    return __half22float2(*(__half2*)&u);
}

#define G_STRIDE 68
#define W_STRIDE 72

// ---------------- k_detect ----------------
__global__ void __launch_bounds__(256) k_detect(const void* __restrict__ ei) {
    int t = threadIdx.x;
#pragma unroll
    for (int r = 0; r < 32; r++)
        ((int4*)d_deg)[t + 256 * r] = make_int4(0, 0, 0, 0);
    __shared__ int bad;
    if (t == 0) bad = 0;
    __syncthreads();
    if (t < 128) {
        long long v = ((const long long*)ei)[t];
        if (v < 0 || v >= NPTS) atomicOr(&bad, 1);
    }
    __syncthreads();
    if (t == 0) d_is64 = bad ? 0 : 1;
}

// ---------------- k_count ----------------
__global__ void k_count(const void* __restrict__ ei) {
    int e = blockIdx.x * blockDim.x + threadIdx.x;
    if (e < NEDGE) {
        int dd = d_is64 ? (int)((const long long*)ei)[NEDGE + e]
                        : ((const int*)ei)[NEDGE + e];
        atomicAdd(&d_deg[dd], 1);
    }
}

// ---------------- k_scan ----------------
__global__ void __launch_bounds__(1024) k_scan() {
    __shared__ int wsum[32];
    int t = threadIdx.x, lane = t & 31, warp = t >> 5;
    int base = t * 32;
    int v[32];
    int s = 0;
#pragma unroll
    for (int i = 0; i < 32; i++) { v[i] = d_deg[base + i]; s += v[i]; }
    int sc = s;
#pragma unroll
    for (int o = 1; o < 32; o <<= 1) {
        int n = __shfl_up_sync(0xffffffffu, sc, o);
        if (lane >= o) sc += n;
    }
    if (lane == 31) wsum[warp] = sc;
    __syncthreads();
    if (warp == 0) {
        int ws = wsum[lane];
#pragma unroll
        for (int o = 1; o < 32; o <<= 1) {
            int n = __shfl_up_sync(0xffffffffu, ws, o);
            if (lane >= o) ws += n;
        }
        wsum[lane] = ws;
    }
    __syncthreads();
    int off = (warp > 0 ? wsum[warp - 1] : 0) + (sc - s);
#pragma unroll
    for (int i = 0; i < 32; i++) {
        d_cursor[base + i] = off;
        d_invc[base + i] = 1.0f / fmaxf((float)v[i], 1.0f);
        off += v[i];
    }
}

// ---------------- k_sortz: sorted edges + zero agg ----------------
__global__ void __launch_bounds__(256) k_sortz(const void* __restrict__ ei) {
    int e = blockIdx.x * 256 + threadIdx.x;
    int is64 = d_is64;
    int ss, dd;
    if (is64) {
        ss = (int)((const long long*)ei)[e];
        dd = (int)((const long long*)ei)[NEDGE + e];
    } else {
        ss = ((const int*)ei)[e];
        dd = ((const int*)ei)[NEDGE + e];
    }
    int p = atomicAdd(&d_cursor[dd], 1);
    d_ssrc[p] = ss;
    d_sdst[p] = dd;
    ((float4*)d_agg)[e] = make_float4(0.f, 0.f, 0.f, 0.f);
    ((float4*)d_agg)[e + NEDGE] = make_float4(0.f, 0.f, 0.f, 0.f);
}

// ---------------- k_lift ----------------
#define LIFT_IN   0
#define LIFT_B2   3072
#define LIFT_TS   3328
#define LIFT_WS   (3328 + 34816)
#define LIFT_SMEM (LIFT_WS + 18432)

__global__ void __launch_bounds__(256) k_lift(
    const float* __restrict__ x, const float* __restrict__ pos,
    const float* __restrict__ w1, const float* __restrict__ b1,
    const float* __restrict__ w2, const float* __restrict__ b2)
{
    extern __shared__ char smem[];
    float*    in_s = (float*)(smem + LIFT_IN);
    float*    b2_s = (float*)(smem + LIFT_B2);
    uint32_t* t_s  = (uint32_t*)(smem + LIFT_TS);
    float*    t_sf = (float*)(smem + LIFT_TS);
    uint32_t* w_s  = (uint32_t*)(smem + LIFT_WS);

    int t = threadIdx.x;
    int item0 = blockIdx.x * 128;

    for (int idx = t; idx < 640; idx += 256) {
        int j = idx / 5, i = idx % 5;
        int item = item0 + j;
        int b = item >> 15, n = item & (NPTS - 1);
        in_s[j * 6 + i] = (i < 3) ? x[((size_t)b * NPTS + n) * 3 + i] : pos[n * 2 + (i - 3)];
    }
    if (t < 64) b2_s[t] = b2[t];
    __syncthreads();

    int c  = t & 63, jg = t >> 6;
    int w  = t >> 5, lane = t & 31;
    int r  = lane >> 2, c4 = lane & 3;
    int m0 = w * 16;

    float acc[8][4];
#pragma unroll
    for (int j = 0; j < 8; j++)
        acc[j][0] = acc[j][1] = acc[j][2] = acc[j][3] = 0.f;

    for (int ch = 0; ch < 4; ch++) {
        int cc = ch * 64 + c;
        float w0 = w1[cc], wA = w1[LIFTD + cc], wB = w1[2 * LIFTD + cc];
        float wC = w1[3 * LIFTD + cc], wD = w1[4 * LIFTD + cc];
        float bc = b1[cc];
#pragma unroll 4
        for (int rr = 0; rr < 32; rr++) {
            int row = jg * 32 + rr;
            const float* in = in_s + row * 6;
            float v = bc + in[0] * w0 + in[1] * wA + in[2] * wB + in[3] * wC + in[4] * wD;
            t_s[row * G_STRIDE + c] = f2tf32(gelu_fast(v));
        }
        for (int idx = t; idx < 4096; idx += 256) {
            int k = idx >> 6, n = idx & 63;
            w_s[k * W_STRIDE + n] = f2tf32(w2[(ch * 64 + k) * HID + n]);
        }
        __syncthreads();

#pragma unroll
        for (int kk = 0; kk < 8; kk++) {
            uint32_t a[4];
            a[0] = t_s[(m0 + r)     * G_STRIDE + kk * 8 + c4];
            a[1] = t_s[(m0 + r + 8) * G_STRIDE + kk * 8 + c4];
            a[2] = t_s[(m0 + r)     * G_STRIDE + kk * 8 + c4 + 4];
            a[3] = t_s[(m0 + r + 8) * G_STRIDE + kk * 8 + c4 + 4];
#pragma unroll
            for (int j = 0; j < 8; j++) {
                uint32_t bb[2];
                bb[0] = w_s[(kk * 8 + c4)     * W_STRIDE + j * 8 + r];
                bb[1] = w_s[(kk * 8 + c4 + 4) * W_STRIDE + j * 8 + r];
                mma_tf32(acc[j], a, bb);
            }
        }
        __syncthreads();
    }

#pragma unroll
    for (int j = 0; j < 8; j++) {
        int col = j * 8 + c4 * 2;
        float b0 = b2_s[col], b1v = b2_s[col + 1];
        *(float2*)(t_sf + (m0 + r)     * G_STRIDE + col) = make_float2(acc[j][0] + b0, acc[j][1] + b1v);
        *(float2*)(t_sf + (m0 + r + 8) * G_STRIDE + col) = make_float2(acc[j][2] + b0, acc[j][3] + b1v);
    }
    __syncthreads();
    for (int idx = t; idx < 8192; idx += 256) {
        int row = idx >> 6, cc = idx & 63;
        d_h[(size_t)(item0 + row) * 64 + cc] = t_sf[row * G_STRIDE + cc];
    }
}

// ---------------- k_APd: fused (G@W2 update) + Pd + (h@W1 -> A) ----------
#define APD_POS  0
#define APD_PW   1024
#define APD_KB2  2048
#define APD_HS   2304
#define APD_WS   (2304 + 34816)
#define APD_SMEM (APD_WS + 18432)

__global__ void __launch_bounds__(256) k_APd(
    const float* __restrict__ pos, const float* __restrict__ kW1_l,
    const float* __restrict__ kb1_l, const float* __restrict__ kW2_p,
    const float* __restrict__ kb2_p, int do_upd)
{
    extern __shared__ char smem[];
    float*    pos_s  = (float*)(smem + APD_POS);
    float*    pw_s   = (float*)(smem + APD_PW);
    float*    kb2_s  = (float*)(smem + APD_KB2);
    uint32_t* h_s    = (uint32_t*)(smem + APD_HS);
    uint32_t* w_s    = (uint32_t*)(smem + APD_WS);

    int t = threadIdx.x;
    int item0 = blockIdx.x * 128;
    int w = t >> 5, lane = t & 31;
    int r = lane >> 2, c4 = lane & 3;
    int m0 = w * 16;

    if (t < 256) {
        int j = t >> 1, i = t & 1;
        int n = (item0 + j) & (NPTS - 1);
        pos_s[j * 2 + i] = pos[n * 2 + i];
    }
    if (t < 256) pw_s[t] = kW1_l[t];
    if (do_upd && t < 64) kb2_s[t] = kb2_p[t];

    if (do_upd) {
#pragma unroll 4
        for (int i = 0; i < 16; i++) {
            int row = m0 + i;
            size_t gi = (size_t)(item0 + row) * 64;
            float g0 = d_agg[gi + lane], g1 = d_agg[gi + 32 + lane];
            d_agg[gi + lane] = 0.f;
            d_agg[gi + 32 + lane] = 0.f;
            h_s[row * G_STRIDE + lane] = f2tf32(g0);
            h_s[row * G_STRIDE + 32 + lane] = f2tf32(g1);
        }
        for (int idx = t; idx < 4096; idx += 256) {
            int k = idx >> 6, n = idx & 63;
            w_s[k * W_STRIDE + n] = f2tf32(kW2_p[k * 64 + n]);
        }
        __syncthreads();

        float acc[8][4];
#pragma unroll
        for (int j = 0; j < 8; j++)
            acc[j][0] = acc[j][1] = acc[j][2] = acc[j][3] = 0.f;
#pragma unroll
        for (int kk = 0; kk < 8; kk++) {
            uint32_t a[4];
            a[0] = h_s[(m0 + r)     * G_STRIDE + kk * 8 + c4];
            a[1] = h_s[(m0 + r + 8) * G_STRIDE + kk * 8 + c4];
            a[2] = h_s[(m0 + r)     * G_STRIDE + kk * 8 + c4 + 4];
            a[3] = h_s[(m0 + r + 8) * G_STRIDE + kk * 8 + c4 + 4];
#pragma unroll
            for (int j = 0; j < 8; j++) {
                uint32_t bb[2];
                bb[0] = w_s[(kk * 8 + c4)     * W_STRIDE + j * 8 + r];
                bb[1] = w_s[(kk * 8 + c4 + 4) * W_STRIDE + j * 8 + r];
                mma_tf32(acc[j], a, bb);
            }
        }
        __syncwarp();

        int nA = (item0 + m0 + r) & (NPTS - 1);
        int nB = (item0 + m0 + r + 8) & (NPTS - 1);
        float iA = d_invc[nA], dA = (float)d_deg[nA];
        float iB = d_invc[nB], dB = (float)d_deg[nB];
        size_t gA = (size_t)(item0 + m0 + r) * 64;
        size_t gB = (size_t)(item0 + m0 + r + 8) * 64;
#pragma unroll
        for (int j = 0; j < 8; j++) {
            int col = j * 8 + c4 * 2;
            float k0 = kb2_s[col], k1 = kb2_s[col + 1];
            float2 hA = *(float2*)(d_h + gA + col);
            float2 hB = *(float2*)(d_h + gB + col);
            float a0 = hA.x + (acc[j][0] + dA * k0) * iA;
            float a1 = hA.y + (acc[j][1] + dA * k1) * iA;
            float b0 = hB.x + (acc[j][2] + dB * k0) * iB;
            float b1 = hB.y + (acc[j][3] + dB * k1) * iB;
            *(float2*)(d_h + gA + col) = make_float2(a0, a1);
            *(float2*)(d_h + gB + col) = make_float2(b0, b1);
            h_s[(m0 + r) * G_STRIDE + col]     = f2tf32(a0);
            h_s[(m0 + r) * G_STRIDE + col + 1] = f2tf32(a1);
            h_s[(m0 + r + 8) * G_STRIDE + col]     = f2tf32(b0);
            h_s[(m0 + r + 8) * G_STRIDE + col + 1] = f2tf32(b1);
        }
        __syncthreads();
    } else {
        for (int idx = t; idx < 8192; idx += 256) {
            int row = idx >> 6, k = idx & 63;
            h_s[row * G_STRIDE + k] = f2tf32(d_h[(size_t)(item0 + row) * 64 + k]);
        }
    }

    for (int idx = t; idx < 4096; idx += 256) {
        int k = idx >> 6, n = idx & 63;
        w_s[k * W_STRIDE + n] = f2tf32(kW1_l[(4 + k) * 64 + n]);
    }
    __syncthreads();

    if (item0 < NPTS) {
        for (int idx = t; idx < 4096; idx += 256) {
            int row = idx >> 5, c2 = idx & 31;
            int n = item0 + row, c = c2 * 2;
            float p0 = pos_s[row * 2], p1 = pos_s[row * 2 + 1];
            float v0 = kb1_l[c]     + p0 * pw_s[128 + c]     + p1 * pw_s[192 + c];
            float v1 = kb1_l[c + 1] + p0 * pw_s[128 + c + 1] + p1 * pw_s[192 + c + 1];
            d_Pdh[(size_t)n * 32 + c2] = pack_h2(v0, v1);
        }
    }

    float acc[8][4];
#pragma unroll
    for (int j = 0; j < 8; j++)
        acc[j][0] = acc[j][1] = acc[j][2] = acc[j][3] = 0.f;
#pragma unroll
    for (int kk = 0; kk < 8; kk++) {
        uint32_t a[4];
        a[0] = h_s[(m0 + r)     * G_STRIDE + kk * 8 + c4];
        a[1] = h_s[(m0 + r + 8) * G_STRIDE + kk * 8 + c4];
        a[2] = h_s[(m0 + r)     * G_STRIDE + kk * 8 + c4 + 4];
        a[3] = h_s[(m0 + r + 8) * G_STRIDE + kk * 8 + c4 + 4];
#pragma unroll
        for (int j = 0; j < 8; j++) {
            uint32_t bb[2];
            bb[0] = w_s[(kk * 8 + c4)     * W_STRIDE + j * 8 + r];
            bb[1] = w_s[(kk * 8 + c4 + 4) * W_STRIDE + j * 8 + r];
            mma_tf32(acc[j], a, bb);
        }
    }
    __syncthreads();

    float p00 = pos_s[(m0 + r) * 2],     p01 = pos_s[(m0 + r) * 2 + 1];
    float p10 = pos_s[(m0 + r + 8) * 2], p11 = pos_s[(m0 + r + 8) * 2 + 1];
#pragma unroll
    for (int j = 0; j < 8; j++) {
        int col = j * 8 + c4 * 2;
        float w00 = pw_s[col], w01 = pw_s[col + 1];
        float w10 = pw_s[64 + col], w11 = pw_s[64 + col + 1];
        h_s[(m0 + r) * 36 + j * 4 + c4] =
            pack_h2(acc[j][0] + p00 * w00 + p01 * w10, acc[j][1] + p00 * w01 + p01 * w11);
        h_s[(m0 + r + 8) * 36 + j * 4 + c4] =
            pack_h2(acc[j][2] + p10 * w00 + p11 * w10, acc[j][3] + p10 * w01 + p11 * w11);
    }
    __syncthreads();
    for (int idx = t; idx < 4096; idx += 256) {
        int row = idx >> 5, cc = idx & 31;
        d_Ah[(size_t)(item0 + row) * 32 + cc] = h_s[row * 36 + cc];
    }
}

// ---------------- k_edge: gather+gelu+scatter, both batches fused ---------
// 512 edges/block, 64 edges/warp, lane = channel pair. 3 LDG/edge (A0,A1,Pd).
__global__ void __launch_bounds__(256) k_edge()
{
    __shared__ int src_s[512];
    __shared__ int dst_s[512];

    int t = threadIdx.x;
    int e_base = blockIdx.x * 512;
    src_s[t]       = d_ssrc[e_base + t];
    src_s[t + 256] = d_ssrc[e_base + 256 + t];
    dst_s[t]       = d_sdst[e_base + t];
    dst_s[t + 256] = d_sdst[e_base + 256 + t];
    __syncthreads();

    int w = t >> 5, lane = t & 31;
    int eb = w * 64;

    const uint32_t* A0 = d_Ah;
    const uint32_t* A1 = d_Ah + (size_t)NPTS * 32;
    float* g0 = d_agg;
    float* g1 = d_agg + (size_t)NPTS * 64;

    int   cur = dst_s[eb];
    float a00 = 0.f, a01 = 0.f, a10 = 0.f, a11 = 0.f;
#pragma unroll 4
    for (int e = 0; e < 64; e++) {
        int ss = src_s[eb + e], dd = dst_s[eb + e];
        uint32_t pd  = __ldg(&d_Pdh[(size_t)dd * 32 + lane]);
        uint32_t av0 = __ldg(&A0[(size_t)ss * 32 + lane]);
        uint32_t av1 = __ldg(&A1[(size_t)ss * 32 + lane]);
        __half2 s0 = __hadd2(*(__half2*)&av0, *(__half2*)&pd);
        __half2 s1 = __hadd2(*(__half2*)&av1, *(__half2*)&pd);
        float2 f0 = unpack_h2(gelu_h2(*(uint32_t*)&s0));
        float2 f1 = unpack_h2(gelu_h2(*(uint32_t*)&s1));
        if (dd != cur) {
            red2(g0 + (size_t)cur * 64 + lane * 2, a00, a01);
            red2(g1 + (size_t)cur * 64 + lane * 2, a10, a11);
            cur = dd;
            a00 = f0.x; a01 = f0.y; a10 = f1.x; a11 = f1.y;
        } else {
            a00 += f0.x; a01 += f0.y; a10 += f1.x; a11 += f1.y;
        }
    }
    red2(g0 + (size_t)cur * 64 + lane * 2, a00, a01);
    red2(g1 + (size_t)cur * 64 + lane * 2, a10, a11);
}

// ---------------- k_proj: fused (G@W2 update) + proj MLP ------------------
#define PROJ_HS   0
#define PROJ_WS   34816
#define PROJ_W2   (34816 + 18432)
#define PROJ_B1   (PROJ_W2 + 1024)
#define PROJ_KB2  (PROJ_B1 + 1024)
#define PROJ_SMEM (PROJ_KB2 + 256)

__global__ void __launch_bounds__(256) k_proj(
    const float* __restrict__ w1, const float* __restrict__ b1,
    const float* __restrict__ w2, const float* __restrict__ b2,
    const float* __restrict__ kW2_p, const float* __restrict__ kb2_p,
    float* __restrict__ out)
{
    extern __shared__ char smem[];
    uint32_t* h_s   = (uint32_t*)(smem + PROJ_HS);
    uint32_t* w_s   = (uint32_t*)(smem + PROJ_WS);
    float*    w2_s  = (float*)(smem + PROJ_W2);
    float*    b1_s  = (float*)(smem + PROJ_B1);
    float*    kb2_s = (float*)(smem + PROJ_KB2);

    int t = threadIdx.x;
    int item0 = blockIdx.x * 128;
    int w = t >> 5, lane = t & 31;
    int r = lane >> 2, c4 = lane & 3;
    int m0 = w * 16;

    w2_s[t] = w2[t];
    b1_s[t] = b1[t];
    if (t < 64) kb2_s[t] = kb2_p[t];

#pragma unroll 4
    for (int i = 0; i < 16; i++) {
        int row = m0 + i;
        size_t gi = (size_t)(item0 + row) * 64;
        h_s[row * G_STRIDE + lane]      = f2tf32(d_agg[gi + lane]);
        h_s[row * G_STRIDE + 32 + lane] = f2tf32(d_agg[gi + 32 + lane]);
    }
    for (int idx = t; idx < 4096; idx += 256) {
        int k = idx >> 6, n = idx & 63;
        w_s[k * W_STRIDE + n] = f2tf32(kW2_p[k * 64 + n]);
    }
    __syncthreads();

    {
        float acc[8][4];
#pragma unroll
        for (int j = 0; j < 8; j++)
            acc[j][0] = acc[j][1] = acc[j][2] = acc[j][3] = 0.f;
#pragma unroll
        for (int kk = 0; kk < 8; kk++) {
            uint32_t a[4];
            a[0] = h_s[(m0 + r)     * G_STRIDE + kk * 8 + c4];
            a[1] = h_s[(m0 + r + 8) * G_STRIDE + kk * 8 + c4];
            a[2] = h_s[(m0 + r)     * G_STRIDE + kk * 8 + c4 + 4];
            a[3] = h_s[(m0 + r + 8) * G_STRIDE + kk * 8 + c4 + 4];
#pragma unroll
            for (int j = 0; j < 8; j++) {
                uint32_t bb[2];
                bb[0] = w_s[(kk * 8 + c4)     * W_STRIDE + j * 8 + r];
                bb[1] = w_s[(kk * 8 + c4 + 4) * W_STRIDE + j * 8 + r];
                mma_tf32(acc[j], a, bb);
            }
        }
        __syncwarp();

        int nA = (item0 + m0 + r) & (NPTS - 1);
        int nB = (item0 + m0 + r + 8) & (NPTS - 1);
        float iA = d_invc[nA], dA = (float)d_deg[nA];
        float iB = d_invc[nB], dB = (float)d_deg[nB];
        size_t gA = (size_t)(item0 + m0 + r) * 64;
        size_t gB = (size_t)(item0 + m0 + r + 8) * 64;
#pragma unroll
        for (int j = 0; j < 8; j++) {
            int col = j * 8 + c4 * 2;
            float k0 = kb2_s[col], k1 = kb2_s[col + 1];
            float2 hA = *(float2*)(d_h + gA + col);
            float2 hB = *(float2*)(d_h + gB + col);
            h_s[(m0 + r) * G_STRIDE + col]     = f2tf32(hA.x + (acc[j][0] + dA * k0) * iA);
            h_s[(m0 + r) * G_STRIDE + col + 1] = f2tf32(hA.y + (acc[j][1] + dA * k1) * iA);
            h_s[(m0 + r + 8) * G_STRIDE + col]     = f2tf32(hB.x + (acc[j][2] + dB * k0) * iB);
            h_s[(m0 + r + 8) * G_STRIDE + col + 1] = f2tf32(hB.y + (acc[j][3] + dB * k1) * iB);
        }
        __syncwarp();
    }

    uint32_t a[8][4];
#pragma unroll
    for (int kk = 0; kk < 8; kk++) {
        a[kk][0] = h_s[(m0 + r)     * G_STRIDE + kk * 8 + c4];
        a[kk][1] = h_s[(m0 + r + 8) * G_STRIDE + kk * 8 + c4];
        a[kk][2] = h_s[(m0 + r)     * G_STRIDE + kk * 8 + c4 + 4];
        a[kk][3] = h_s[(m0 + r + 8) * G_STRIDE + kk * 8 + c4 + 4];
    }

    float sum0 = 0.f, sum1 = 0.f;
    for (int ch = 0; ch < 4; ch++) {
        __syncthreads();
        for (int idx = t; idx < 4096; idx += 256) {
            int k = idx >> 6, n = idx & 63;
            w_s[k * W_STRIDE + n] = f2tf32(w1[k * 256 + ch * 64 + n]);
        }
        __syncthreads();

        float acc[8][4];
#pragma unroll
        for (int j = 0; j < 8; j++)
            acc[j][0] = acc[j][1] = acc[j][2] = acc[j][3] = 0.f;
#pragma unroll
        for (int kk = 0; kk < 8; kk++) {
#pragma unroll
            for (int j = 0; j < 8; j++) {
                uint32_t bb[2];
                bb[0] = w_s[(kk * 8 + c4)     * W_STRIDE + j * 8 + r];
                bb[1] = w_s[(kk * 8 + c4 + 4) * W_STRIDE + j * 8 + r];
                mma_tf32(acc[j], a[kk], bb);
            }
        }
#pragma unroll
        for (int j = 0; j < 8; j++) {
            int col = ch * 64 + j * 8 + c4 * 2;
            sum0 += gelu_fast(acc[j][0] + b1_s[col]) * w2_s[col]
                  + gelu_fast(acc[j][1] + b1_s[col + 1]) * w2_s[col + 1];
            sum1 += gelu_fast(acc[j][2] + b1_s[col]) * w2_s[col]
                  + gelu_fast(acc[j][3] + b1_s[col + 1]) * w2_s[col + 1];
        }
    }

    sum0 += __shfl_xor_sync(0xffffffffu, sum0, 1);
    sum0 += __shfl_xor_sync(0xffffffffu, sum0, 2);
    sum1 += __shfl_xor_sync(0xffffffffu, sum1, 1);
    sum1 += __shfl_xor_sync(0xffffffffu, sum1, 2);
    if (c4 == 0) {
        float bb = b2[0];
        out[item0 + m0 + r]     = sum0 + bb;
        out[item0 + m0 + r + 8] = sum1 + bb;
    }
}

// ---------------- launch ----------------
extern "C" void kernel_launch(void* const* d_in, const int* in_sizes, int n_in,
                              void* d_out, int out_size) {
    (void)in_sizes; (void)n_in; (void)out_size;
    const float* x    = (const float*)d_in[0];
    const float* pos  = (const float*)d_in[1];
    const void*  ei   = d_in[2];
    const float* lw1  = (const float*)d_in[3];
    const float* lb1  = (const float*)d_in[4];
    const float* lw2  = (const float*)d_in[5];
    const float* lb2  = (const float*)d_in[6];
    const float* kW1  = (const float*)d_in[7];
    const float* kb1  = (const float*)d_in[8];
    const float* kW2  = (const float*)d_in[9];
    const float* kb2  = (const float*)d_in[10];
    const float* pw1  = (const float*)d_in[11];
    const float* pb1  = (const float*)d_in[12];
    const float* pw2  = (const float*)d_in[13];
    const float* pb2  = (const float*)d_in[14];
    float* out = (float*)d_out;

    cudaFuncSetAttribute(k_lift, cudaFuncAttributeMaxDynamicSharedMemorySize, LIFT_SMEM);
    cudaFuncSetAttribute(k_APd,  cudaFuncAttributeMaxDynamicSharedMemorySize, APD_SMEM);
    cudaFuncSetAttribute(k_proj, cudaFuncAttributeMaxDynamicSharedMemorySize, PROJ_SMEM);

    k_detect<<<1, 256>>>(ei);
    k_count<<<NEDGE / 256, 256>>>(ei);
    k_scan<<<1, 1024>>>();
    k_sortz<<<NEDGE / 256, 256>>>(ei);
    k_lift<<<(NBATCH * NPTS) / 128, 256, LIFT_SMEM>>>(x, pos, lw1, lb1, lw2, lb2);

    for (int l = 0; l < NLAYER; l++) {
        const float* W1l = kW1 + (size_t)l * 68 * 64;
        const float* b1l = kb1 + (size_t)l * 64;
        const float* W2p = kW2 + (size_t)(l - 1) * 64 * 64;   // unused when l==0
        const float* b2p = kb2 + (size_t)(l - 1) * 64;
        k_APd<<<(NBATCH * NPTS) / 128, 256, APD_SMEM>>>(
            pos, W1l, b1l, l > 0 ? W2p : kW2, l > 0 ? b2p : kb2, l > 0);
        k_edge<<<NEDGE / 512, 256>>>();
    }

    k_proj<<<(NBATCH * NPTS) / 128, 256, PROJ_SMEM>>>(
        pw1, pb1, pw2, pb2,
        kW2 + (size_t)(NLAYER - 1) * 64 * 64, kb2 + (size_t)(NLAYER - 1) * 64, out);
}

// round 14
// speedup vs baseline: 1.6963x; 1.2146x over previous
#include <cuda_runtime.h>
#include <cuda_fp16.h>
#include <math.h>
#include <stdint.h>

#define NPTS   32768
#define NEDGE  524288
#define NBATCH 2
#define HID    64
#define LIFTD  256
#define NLAYER 4

// ---------------- scratch ----------------
__device__ float    d_h[NBATCH * NPTS * HID];
__device__ uint32_t d_Ah[NBATCH * NPTS * 32];   // half2-packed A
__device__ uint32_t d_Pdh[NPTS * 32];           // half2-packed Pd
__device__ float    d_agg[NBATCH * NPTS * HID]; // G = sum of gelu (pre-W2)
__device__ float    d_invc[NPTS];
__device__ int      d_deg[NPTS];
__device__ int      d_off[NPTS];                // exclusive CSR offsets
__device__ int      d_cursor[NPTS];
__device__ int      d_ssrc[NEDGE];
__device__ int      d_sdst[NEDGE];
__device__ int      d_is64;

// fast tanh-form gelu (fp32)
__device__ __forceinline__ float gelu_fast(float x) {
    float x2 = x * x;
    float inner = x * fmaf(0.0356774081f, x2, 0.7978845608f);
    float t;
    asm("tanh.approx.f32 %0, %1;" : "=f"(t) : "f"(inner));
    float hx = 0.5f * x;
    return fmaf(hx, t, hx);
}
// packed half2 tanh-form gelu
__device__ __forceinline__ uint32_t gelu_h2(uint32_t xu) {
    __half2 x = *(__half2*)&xu;
    const __half2 c1 = __floats2half2_rn(0.0356774081f, 0.0356774081f);
    const __half2 c0 = __floats2half2_rn(0.7978845608f, 0.7978845608f);
    const __half2 hf = __floats2half2_rn(0.5f, 0.5f);
    __half2 x2 = __hmul2(x, x);
    __half2 inner = __hmul2(x, __hfma2(c1, x2, c0));
    uint32_t tu;
    asm("tanh.approx.f16x2 %0, %1;" : "=r"(tu) : "r"(*(uint32_t*)&inner));
    __half2 hx = __hmul2(hf, x);
    __half2 res = __hfma2(hx, *(__half2*)&tu, hx);
    return *(uint32_t*)&res;
}
__device__ __forceinline__ uint32_t f2tf32(float f) {
    uint32_t r;
    asm("cvt.rna.tf32.f32 %0, %1;" : "=r"(r) : "f"(f));
    return r;
}
__device__ __forceinline__ void mma_tf32(float* d, const uint32_t* a, const uint32_t* b) {
    asm volatile("mma.sync.aligned.m16n8k8.row.col.f32.tf32.tf32.f32 "
                 "{%0,%1,%2,%3}, {%4,%5,%6,%7}, {%8,%9}, {%0,%1,%2,%3};"
                 : "+f"(d[0]), "+f"(d[1]), "+f"(d[2]), "+f"(d[3])
                 : "r"(a[0]), "r"(a[1]), "r"(a[2]), "r"(a[3]), "r"(b[0]), "r"(b[1]));
}
__device__ __forceinline__ uint32_t pack_h2(float a, float b) {
    __half2 h = __floats2half2_rn(a, b);
    return *(uint32_t*)&h;
}
__device__ __forceinline__ float2 unpack_h2(uint32_t u) {
    return __half22float2(*(__half2*)&u);
}

#define G_STRIDE 68
#define W_STRIDE 72

// ---------------- k_detect ----------------
__global__ void __launch_bounds__(256) k_detect(const void* __restrict__ ei) {
    int t = threadIdx.x;
#pragma unroll
    for (int r = 0; r < 32; r++)
        ((int4*)d_deg)[t + 256 * r] = make_int4(0, 0, 0, 0);
    __shared__ int bad;
    if (t == 0) bad = 0;
    __syncthreads();
    if (t < 128) {
        long long v = ((const long long*)ei)[t];
        if (v < 0 || v >= NPTS) atomicOr(&bad, 1);
    }
    __syncthreads();
    if (t == 0) d_is64 = bad ? 0 : 1;
}

// ---------------- k_count ----------------
__global__ void k_count(const void* __restrict__ ei) {
    int e = blockIdx.x * blockDim.x + threadIdx.x;
    if (e < NEDGE) {
        int dd = d_is64 ? (int)((const long long*)ei)[NEDGE + e]
                        : ((const int*)ei)[NEDGE + e];
        atomicAdd(&d_deg[dd], 1);
    }
}

// ---------------- k_scan ----------------
__global__ void __launch_bounds__(1024) k_scan() {
    __shared__ int wsum[32];
    int t = threadIdx.x, lane = t & 31, warp = t >> 5;
    int base = t * 32;
    int v[32];
    int s = 0;
#pragma unroll
    for (int i = 0; i < 32; i++) { v[i] = d_deg[base + i]; s += v[i]; }
    int sc = s;
#pragma unroll
    for (int o = 1; o < 32; o <<= 1) {
        int n = __shfl_up_sync(0xffffffffu, sc, o);
        if (lane >= o) sc += n;
    }
    if (lane == 31) wsum[warp] = sc;
    __syncthreads();
    if (warp == 0) {
        int ws = wsum[lane];
#pragma unroll
        for (int o = 1; o < 32; o <<= 1) {
            int n = __shfl_up_sync(0xffffffffu, ws, o);
            if (lane >= o) ws += n;
        }
        wsum[lane] = ws;
    }
    __syncthreads();
    int off = (warp > 0 ? wsum[warp - 1] : 0) + (sc - s);
#pragma unroll
    for (int i = 0; i < 32; i++) {
        d_off[base + i] = off;
        d_cursor[base + i] = off;
        d_invc[base + i] = 1.0f / fmaxf((float)v[i], 1.0f);
        off += v[i];
    }
}

// ---------------- k_sortz: sorted edges (no agg zero needed) --------------
__global__ void __launch_bounds__(256) k_sortz(const void* __restrict__ ei) {
    int e = blockIdx.x * 256 + threadIdx.x;
    int is64 = d_is64;
    int ss, dd;
    if (is64) {
        ss = (int)((const long long*)ei)[e];
        dd = (int)((const long long*)ei)[NEDGE + e];
    } else {
        ss = ((const int*)ei)[e];
        dd = ((const int*)ei)[NEDGE + e];
    }
    int p = atomicAdd(&d_cursor[dd], 1);
    d_ssrc[p] = ss;
    d_sdst[p] = dd;
}

// ---------------- k_lift ----------------
#define LIFT_IN   0
#define LIFT_B2   3072
#define LIFT_TS   3328
#define LIFT_WS   (3328 + 34816)
#define LIFT_SMEM (LIFT_WS + 18432)

__global__ void __launch_bounds__(256) k_lift(
    const float* __restrict__ x, const float* __restrict__ pos,
    const float* __restrict__ w1, const float* __restrict__ b1,
    const float* __restrict__ w2, const float* __restrict__ b2)
{
    extern __shared__ char smem[];
    float*    in_s = (float*)(smem + LIFT_IN);
    float*    b2_s = (float*)(smem + LIFT_B2);
    uint32_t* t_s  = (uint32_t*)(smem + LIFT_TS);
    float*    t_sf = (float*)(smem + LIFT_TS);
    uint32_t* w_s  = (uint32_t*)(smem + LIFT_WS);

    int t = threadIdx.x;
    int item0 = blockIdx.x * 128;

    for (int idx = t; idx < 640; idx += 256) {
        int j = idx / 5, i = idx % 5;
        int item = item0 + j;
        int b = item >> 15, n = item & (NPTS - 1);
        in_s[j * 6 + i] = (i < 3) ? x[((size_t)b * NPTS + n) * 3 + i] : pos[n * 2 + (i - 3)];
    }
    if (t < 64) b2_s[t] = b2[t];
    __syncthreads();

    int c  = t & 63, jg = t >> 6;
    int w  = t >> 5, lane = t & 31;
    int r  = lane >> 2, c4 = lane & 3;
    int m0 = w * 16;

    float acc[8][4];
#pragma unroll
    for (int j = 0; j < 8; j++)
        acc[j][0] = acc[j][1] = acc[j][2] = acc[j][3] = 0.f;

    for (int ch = 0; ch < 4; ch++) {
        int cc = ch * 64 + c;
        float w0 = w1[cc], wA = w1[LIFTD + cc], wB = w1[2 * LIFTD + cc];
        float wC = w1[3 * LIFTD + cc], wD = w1[4 * LIFTD + cc];
        float bc = b1[cc];
#pragma unroll 4
        for (int rr = 0; rr < 32; rr++) {
            int row = jg * 32 + rr;
            const float* in = in_s + row * 6;
            float v = bc + in[0] * w0 + in[1] * wA + in[2] * wB + in[3] * wC + in[4] * wD;
            t_s[row * G_STRIDE + c] = f2tf32(gelu_fast(v));
        }
        for (int idx = t; idx < 4096; idx += 256) {
            int k = idx >> 6, n = idx & 63;
            w_s[k * W_STRIDE + n] = f2tf32(w2[(ch * 64 + k) * HID + n]);
        }
        __syncthreads();

#pragma unroll
        for (int kk = 0; kk < 8; kk++) {
            uint32_t a[4];
            a[0] = t_s[(m0 + r)     * G_STRIDE + kk * 8 + c4];
            a[1] = t_s[(m0 + r + 8) * G_STRIDE + kk * 8 + c4];
            a[2] = t_s[(m0 + r)     * G_STRIDE + kk * 8 + c4 + 4];
            a[3] = t_s[(m0 + r + 8) * G_STRIDE + kk * 8 + c4 + 4];
#pragma unroll
            for (int j = 0; j < 8; j++) {
                uint32_t bb[2];
                bb[0] = w_s[(kk * 8 + c4)     * W_STRIDE + j * 8 + r];
                bb[1] = w_s[(kk * 8 + c4 + 4) * W_STRIDE + j * 8 + r];
                mma_tf32(acc[j], a, bb);
            }
        }
        __syncthreads();
    }

#pragma unroll
    for (int j = 0; j < 8; j++) {
        int col = j * 8 + c4 * 2;
        float b0 = b2_s[col], b1v = b2_s[col + 1];
        *(float2*)(t_sf + (m0 + r)     * G_STRIDE + col) = make_float2(acc[j][0] + b0, acc[j][1] + b1v);
        *(float2*)(t_sf + (m0 + r + 8) * G_STRIDE + col) = make_float2(acc[j][2] + b0, acc[j][3] + b1v);
    }
    __syncthreads();
    for (int idx = t; idx < 8192; idx += 256) {
        int row = idx >> 6, cc = idx & 63;
        d_h[(size_t)(item0 + row) * 64 + cc] = t_sf[row * G_STRIDE + cc];
    }
}

// ---------------- k_APd: fused (G@W2 update) + Pd + (h@W1 -> A) ----------
#define APD_POS  0
#define APD_PW   1024
#define APD_KB2  2048
#define APD_HS   2304
#define APD_WS   (2304 + 34816)
#define APD_SMEM (APD_WS + 18432)

__global__ void __launch_bounds__(256) k_APd(
    const float* __restrict__ pos, const float* __restrict__ kW1_l,
    const float* __restrict__ kb1_l, const float* __restrict__ kW2_p,
    const float* __restrict__ kb2_p, int do_upd)
{
    extern __shared__ char smem[];
    float*    pos_s  = (float*)(smem + APD_POS);
    float*    pw_s   = (float*)(smem + APD_PW);
    float*    kb2_s  = (float*)(smem + APD_KB2);
    uint32_t* h_s    = (uint32_t*)(smem + APD_HS);
    uint32_t* w_s    = (uint32_t*)(smem + APD_WS);

    int t = threadIdx.x;
    int item0 = blockIdx.x * 128;
    int w = t >> 5, lane = t & 31;
    int r = lane >> 2, c4 = lane & 3;
    int m0 = w * 16;

    if (t < 256) {
        int j = t >> 1, i = t & 1;
        int n = (item0 + j) & (NPTS - 1);
        pos_s[j * 2 + i] = pos[n * 2 + i];
    }
    if (t < 256) pw_s[t] = kW1_l[t];
    if (do_upd && t < 64) kb2_s[t] = kb2_p[t];

    if (do_upd) {
#pragma unroll 4
        for (int i = 0; i < 16; i++) {
            int row = m0 + i;
            size_t gi = (size_t)(item0 + row) * 64;
            h_s[row * G_STRIDE + lane]      = f2tf32(d_agg[gi + lane]);
            h_s[row * G_STRIDE + 32 + lane] = f2tf32(d_agg[gi + 32 + lane]);
        }
        for (int idx = t; idx < 4096; idx += 256) {
            int k = idx >> 6, n = idx & 63;
            w_s[k * W_STRIDE + n] = f2tf32(kW2_p[k * 64 + n]);
        }
        __syncthreads();

        float acc[8][4];
#pragma unroll
        for (int j = 0; j < 8; j++)
            acc[j][0] = acc[j][1] = acc[j][2] = acc[j][3] = 0.f;
#pragma unroll
        for (int kk = 0; kk < 8; kk++) {
            uint32_t a[4];
            a[0] = h_s[(m0 + r)     * G_STRIDE + kk * 8 + c4];
            a[1] = h_s[(m0 + r + 8) * G_STRIDE + kk * 8 + c4];
            a[2] = h_s[(m0 + r)     * G_STRIDE + kk * 8 + c4 + 4];
            a[3] = h_s[(m0 + r + 8) * G_STRIDE + kk * 8 + c4 + 4];
#pragma unroll
            for (int j = 0; j < 8; j++) {
                uint32_t bb[2];
                bb[0] = w_s[(kk * 8 + c4)     * W_STRIDE + j * 8 + r];
                bb[1] = w_s[(kk * 8 + c4 + 4) * W_STRIDE + j * 8 + r];
                mma_tf32(acc[j], a, bb);
            }
        }
        __syncwarp();

        int nA = (item0 + m0 + r) & (NPTS - 1);
        int nB = (item0 + m0 + r + 8) & (NPTS - 1);
        float iA = d_invc[nA], dA = (float)d_deg[nA];
        float iB = d_invc[nB], dB = (float)d_deg[nB];
        size_t gA = (size_t)(item0 + m0 + r) * 64;
        size_t gB = (size_t)(item0 + m0 + r + 8) * 64;
#pragma unroll
        for (int j = 0; j < 8; j++) {
            int col = j * 8 + c4 * 2;
            float k0 = kb2_s[col], k1 = kb2_s[col + 1];
            float2 hA = *(float2*)(d_h + gA + col);
            float2 hB = *(float2*)(d_h + gB + col);
            float a0 = hA.x + (acc[j][0] + dA * k0) * iA;
            float a1 = hA.y + (acc[j][1] + dA * k1) * iA;
            float b0 = hB.x + (acc[j][2] + dB * k0) * iB;
            float b1 = hB.y + (acc[j][3] + dB * k1) * iB;
            *(float2*)(d_h + gA + col) = make_float2(a0, a1);
            *(float2*)(d_h + gB + col) = make_float2(b0, b1);
            h_s[(m0 + r) * G_STRIDE + col]     = f2tf32(a0);
            h_s[(m0 + r) * G_STRIDE + col + 1] = f2tf32(a1);
            h_s[(m0 + r + 8) * G_STRIDE + col]     = f2tf32(b0);
            h_s[(m0 + r + 8) * G_STRIDE + col + 1] = f2tf32(b1);
        }
        __syncthreads();
    } else {
        for (int idx = t; idx < 8192; idx += 256) {
            int row = idx >> 6, k = idx & 63;
            h_s[row * G_STRIDE + k] = f2tf32(d_h[(size_t)(item0 + row) * 64 + k]);
        }
    }

    for (int idx = t; idx < 4096; idx += 256) {
        int k = idx >> 6, n = idx & 63;
        w_s[k * W_STRIDE + n] = f2tf32(kW1_l[(4 + k) * 64 + n]);
    }
    __syncthreads();

    if (item0 < NPTS) {
        for (int idx = t; idx < 4096; idx += 256) {
            int row = idx >> 5, c2 = idx & 31;
            int n = item0 + row, c = c2 * 2;
            float p0 = pos_s[row * 2], p1 = pos_s[row * 2 + 1];
            float v0 = kb1_l[c]     + p0 * pw_s[128 + c]     + p1 * pw_s[192 + c];
            float v1 = kb1_l[c + 1] + p0 * pw_s[128 + c + 1] + p1 * pw_s[192 + c + 1];
            d_Pdh[(size_t)n * 32 + c2] = pack_h2(v0, v1);
        }
    }

    float acc[8][4];
#pragma unroll
    for (int j = 0; j < 8; j++)
        acc[j][0] = acc[j][1] = acc[j][2] = acc[j][3] = 0.f;
#pragma unroll
    for (int kk = 0; kk < 8; kk++) {
        uint32_t a[4];
        a[0] = h_s[(m0 + r)     * G_STRIDE + kk * 8 + c4];
        a[1] = h_s[(m0 + r + 8) * G_STRIDE + kk * 8 + c4];
        a[2] = h_s[(m0 + r)     * G_STRIDE + kk * 8 + c4 + 4];
        a[3] = h_s[(m0 + r + 8) * G_STRIDE + kk * 8 + c4 + 4];
#pragma unroll
        for (int j = 0; j < 8; j++) {
            uint32_t bb[2];
            bb[0] = w_s[(kk * 8 + c4)     * W_STRIDE + j * 8 + r];
            bb[1] = w_s[(kk * 8 + c4 + 4) * W_STRIDE + j * 8 + r];
            mma_tf32(acc[j], a, bb);
        }
    }
    __syncthreads();

    float p00 = pos_s[(m0 + r) * 2],     p01 = pos_s[(m0 + r) * 2 + 1];
    float p10 = pos_s[(m0 + r + 8) * 2], p11 = pos_s[(m0 + r + 8) * 2 + 1];
#pragma unroll
    for (int j = 0; j < 8; j++) {
        int col = j * 8 + c4 * 2;
        float w00 = pw_s[col], w01 = pw_s[col + 1];
        float w10 = pw_s[64 + col], w11 = pw_s[64 + col + 1];
        h_s[(m0 + r) * 36 + j * 4 + c4] =
            pack_h2(acc[j][0] + p00 * w00 + p01 * w10, acc[j][1] + p00 * w01 + p01 * w11);
        h_s[(m0 + r + 8) * 36 + j * 4 + c4] =
            pack_h2(acc[j][2] + p10 * w00 + p11 * w10, acc[j][3] + p10 * w01 + p11 * w11);
    }
    __syncthreads();
    for (int idx = t; idx < 4096; idx += 256) {
        int row = idx >> 5, cc = idx & 31;
        d_Ah[(size_t)(item0 + row) * 32 + cc] = h_s[row * 36 + cc];
    }
}

// ---------------- k_edge: CSR warp-per-node, no atomics -------------------
// 2 nodes/warp, 16 nodes/block, grid 2048. lane = channel pair.
__global__ void __launch_bounds__(256) k_edge()
{
    int wg = blockIdx.x * 8 + (threadIdx.x >> 5);
    int lane = threadIdx.x & 31;
    const uint32_t* A0 = d_Ah;
    const uint32_t* A1 = d_Ah + (size_t)NPTS * 32;

#pragma unroll
    for (int j = 0; j < 2; j++) {
        int n = wg * 2 + j;
        int len   = d_deg[n];
        int start = d_off[n];
        uint32_t pd = d_Pdh[(size_t)n * 32 + lane];
        __half2 pdh = *(__half2*)&pd;
        float a00 = 0.f, a01 = 0.f, a10 = 0.f, a11 = 0.f;
#pragma unroll 4
        for (int e = 0; e < len; e++) {
            int ss = __ldg(&d_ssrc[start + e]);      // uniform across warp
            uint32_t av0 = __ldg(&A0[(size_t)ss * 32 + lane]);
            uint32_t av1 = __ldg(&A1[(size_t)ss * 32 + lane]);
            __half2 s0 = __hadd2(*(__half2*)&av0, pdh);
            __half2 s1 = __hadd2(*(__half2*)&av1, pdh);
            float2 f0 = unpack_h2(gelu_h2(*(uint32_t*)&s0));
            float2 f1 = unpack_h2(gelu_h2(*(uint32_t*)&s1));
            a00 += f0.x; a01 += f0.y; a10 += f1.x; a11 += f1.y;
        }
        *(float2*)(d_agg + (size_t)n * 64 + lane * 2) = make_float2(a00, a01);
        *(float2*)(d_agg + (size_t)(NPTS + n) * 64 + lane * 2) = make_float2(a10, a11);
    }
}

// ---------------- k_proj: fused (G@W2 update) + proj MLP ------------------
#define PROJ_HS   0
#define PROJ_WS   34816
#define PROJ_W2   (34816 + 18432)
#define PROJ_B1   (PROJ_W2 + 1024)
#define PROJ_KB2  (PROJ_B1 + 1024)
#define PROJ_SMEM (PROJ_KB2 + 256)

__global__ void __launch_bounds__(256) k_proj(
    const float* __restrict__ w1, const float* __restrict__ b1,
    const float* __restrict__ w2, const float* __restrict__ b2,
    const float* __restrict__ kW2_p, const float* __restrict__ kb2_p,
    float* __restrict__ out)
{
    extern __shared__ char smem[];
    uint32_t* h_s   = (uint32_t*)(smem + PROJ_HS);
    uint32_t* w_s   = (uint32_t*)(smem + PROJ_WS);
    float*    w2_s  = (float*)(smem + PROJ_W2);
    float*    b1_s  = (float*)(smem + PROJ_B1);
    float*    kb2_s = (float*)(smem + PROJ_KB2);

    int t = threadIdx.x;
    int item0 = blockIdx.x * 128;
    int w = t >> 5, lane = t & 31;
    int r = lane >> 2, c4 = lane & 3;
    int m0 = w * 16;

    w2_s[t] = w2[t];
    b1_s[t] = b1[t];
    if (t < 64) kb2_s[t] = kb2_p[t];

#pragma unroll 4
    for (int i = 0; i < 16; i++) {
        int row = m0 + i;
        size_t gi = (size_t)(item0 + row) * 64;
        h_s[row * G_STRIDE + lane]      = f2tf32(d_agg[gi + lane]);
        h_s[row * G_STRIDE + 32 + lane] = f2tf32(d_agg[gi + 32 + lane]);
    }
    for (int idx = t; idx < 4096; idx += 256) {
        int k = idx >> 6, n = idx & 63;
        w_s[k * W_STRIDE + n] = f2tf32(kW2_p[k * 64 + n]);
    }
    __syncthreads();

    {
        float acc[8][4];
#pragma unroll
        for (int j = 0; j < 8; j++)
            acc[j][0] = acc[j][1] = acc[j][2] = acc[j][3] = 0.f;
#pragma unroll
        for (int kk = 0; kk < 8; kk++) {
            uint32_t a[4];
            a[0] = h_s[(m0 + r)     * G_STRIDE + kk * 8 + c4];
            a[1] = h_s[(m0 + r + 8) * G_STRIDE + kk * 8 + c4];
            a[2] = h_s[(m0 + r)     * G_STRIDE + kk * 8 + c4 + 4];
            a[3] = h_s[(m0 + r + 8) * G_STRIDE + kk * 8 + c4 + 4];
#pragma unroll
            for (int j = 0; j < 8; j++) {
                uint32_t bb[2];
                bb[0] = w_s[(kk * 8 + c4)     * W_STRIDE + j * 8 + r];
                bb[1] = w_s[(kk * 8 + c4 + 4) * W_STRIDE + j * 8 + r];
                mma_tf32(acc[j], a, bb);
            }
        }
        __syncwarp();

        int nA = (item0 + m0 + r) & (NPTS - 1);
        int nB = (item0 + m0 + r + 8) & (NPTS - 1);
        float iA = d_invc[nA], dA = (float)d_deg[nA];
        float iB = d_invc[nB], dB = (float)d_deg[nB];
        size_t gA = (size_t)(item0 + m0 + r) * 64;
        size_t gB = (size_t)(item0 + m0 + r + 8) * 64;
#pragma unroll
        for (int j = 0; j < 8; j++) {
            int col = j * 8 + c4 * 2;
            float k0 = kb2_s[col], k1 = kb2_s[col + 1];
            float2 hA = *(float2*)(d_h + gA + col);
            float2 hB = *(float2*)(d_h + gB + col);
            h_s[(m0 + r) * G_STRIDE + col]     = f2tf32(hA.x + (acc[j][0] + dA * k0) * iA);
            h_s[(m0 + r) * G_STRIDE + col + 1] = f2tf32(hA.y + (acc[j][1] + dA * k1) * iA);
            h_s[(m0 + r + 8) * G_STRIDE + col]     = f2tf32(hB.x + (acc[j][2] + dB * k0) * iB);
            h_s[(m0 + r + 8) * G_STRIDE + col + 1] = f2tf32(hB.y + (acc[j][3] + dB * k1) * iB);
        }
        __syncwarp();
    }

    uint32_t a[8][4];
#pragma unroll
    for (int kk = 0; kk < 8; kk++) {
        a[kk][0] = h_s[(m0 + r)     * G_STRIDE + kk * 8 + c4];
        a[kk][1] = h_s[(m0 + r + 8) * G_STRIDE + kk * 8 + c4];
        a[kk][2] = h_s[(m0 + r)     * G_STRIDE + kk * 8 + c4 + 4];
        a[kk][3] = h_s[(m0 + r + 8) * G_STRIDE + kk * 8 + c4 + 4];
    }

    float sum0 = 0.f, sum1 = 0.f;
    for (int ch = 0; ch < 4; ch++) {
        __syncthreads();
        for (int idx = t; idx < 4096; idx += 256) {
            int k = idx >> 6, n = idx & 63;
            w_s[k * W_STRIDE + n] = f2tf32(w1[k * 256 + ch * 64 + n]);
        }
        __syncthreads();

        float acc[8][4];
#pragma unroll
        for (int j = 0; j < 8; j++)
            acc[j][0] = acc[j][1] = acc[j][2] = acc[j][3] = 0.f;
#pragma unroll
        for (int kk = 0; kk < 8; kk++) {
#pragma unroll
            for (int j = 0; j < 8; j++) {
                uint32_t bb[2];
                bb[0] = w_s[(kk * 8 + c4)     * W_STRIDE + j * 8 + r];
                bb[1] = w_s[(kk * 8 + c4 + 4) * W_STRIDE + j * 8 + r];
                mma_tf32(acc[j], a[kk], bb);
            }
        }
#pragma unroll
        for (int j = 0; j < 8; j++) {
            int col = ch * 64 + j * 8 + c4 * 2;
            sum0 += gelu_fast(acc[j][0] + b1_s[col]) * w2_s[col]
                  + gelu_fast(acc[j][1] + b1_s[col + 1]) * w2_s[col + 1];
            sum1 += gelu_fast(acc[j][2] + b1_s[col]) * w2_s[col]
                  + gelu_fast(acc[j][3] + b1_s[col + 1]) * w2_s[col + 1];
        }
    }

    sum0 += __shfl_xor_sync(0xffffffffu, sum0, 1);
    sum0 += __shfl_xor_sync(0xffffffffu, sum0, 2);
    sum1 += __shfl_xor_sync(0xffffffffu, sum1, 1);
    sum1 += __shfl_xor_sync(0xffffffffu, sum1, 2);
    if (c4 == 0) {
        float bb = b2[0];
        out[item0 + m0 + r]     = sum0 + bb;
        out[item0 + m0 + r + 8] = sum1 + bb;
    }
}

// ---------------- launch ----------------
extern "C" void kernel_launch(void* const* d_in, const int* in_sizes, int n_in,
                              void* d_out, int out_size) {
    (void)in_sizes; (void)n_in; (void)out_size;
    const float* x    = (const float*)d_in[0];
    const float* pos  = (const float*)d_in[1];
    const void*  ei   = d_in[2];
    const float* lw1  = (const float*)d_in[3];
    const float* lb1  = (const float*)d_in[4];
    const float* lw2  = (const float*)d_in[5];
    const float* lb2  = (const float*)d_in[6];
    const float* kW1  = (const float*)d_in[7];
    const float* kb1  = (const float*)d_in[8];
    const float* kW2  = (const float*)d_in[9];
    const float* kb2  = (const float*)d_in[10];
    const float* pw1  = (const float*)d_in[11];
    const float* pb1  = (const float*)d_in[12];
    const float* pw2  = (const float*)d_in[13];
    const float* pb2  = (const float*)d_in[14];
    float* out = (float*)d_out;

    cudaFuncSetAttribute(k_lift, cudaFuncAttributeMaxDynamicSharedMemorySize, LIFT_SMEM);
    cudaFuncSetAttribute(k_APd,  cudaFuncAttributeMaxDynamicSharedMemorySize, APD_SMEM);
    cudaFuncSetAttribute(k_proj, cudaFuncAttributeMaxDynamicSharedMemorySize, PROJ_SMEM);

    k_detect<<<1, 256>>>(ei);
    k_count<<<NEDGE / 256, 256>>>(ei);
    k_scan<<<1, 1024>>>();
    k_sortz<<<NEDGE / 256, 256>>>(ei);
    k_lift<<<(NBATCH * NPTS) / 128, 256, LIFT_SMEM>>>(x, pos, lw1, lb1, lw2, lb2);

    for (int l = 0; l < NLAYER; l++) {
        const float* W1l = kW1 + (size_t)l * 68 * 64;
        const float* b1l = kb1 + (size_t)l * 64;
        const float* W2p = kW2 + (size_t)(l - 1) * 64 * 64;   // unused when l==0
        const float* b2p = kb2 + (size_t)(l - 1) * 64;
        k_APd<<<(NBATCH * NPTS) / 128, 256, APD_SMEM>>>(
            pos, W1l, b1l, l > 0 ? W2p : kW2, l > 0 ? b2p : kb2, l > 0);
        k_edge<<<NPTS / 16, 256>>>();
    }

    k_proj<<<(NBATCH * NPTS) / 128, 256, PROJ_SMEM>>>(
        pw1, pb1, pw2, pb2,
        kW2 + (size_t)(NLAYER - 1) * 64 * 64, kb2 + (size_t)(NLAYER - 1) * 64, out);
}

// round 15
// speedup vs baseline: 1.9736x; 1.1635x over previous
#include <cuda_runtime.h>
#include <cuda_fp16.h>
#include <math.h>
#include <stdint.h>

#define NPTS   32768
#define NEDGE  524288
#define NBATCH 2
#define HID    64
#define LIFTD  256
#define NLAYER 4

// ---------------- scratch ----------------
__device__ float    d_h[NBATCH * NPTS * HID];
__device__ uint32_t d_Ah[NBATCH * NPTS * 32];   // half2-packed A
__device__ uint32_t d_Pdh[NPTS * 32];           // half2-packed Pd
__device__ float    d_agg[NBATCH * NPTS * HID]; // G = sum of gelu (pre-W2)
__device__ float    d_invc[NPTS];
__device__ int      d_deg[NPTS];
__device__ int      d_off[NPTS];
__device__ int      d_cursor[NPTS];
__device__ int      d_ssrc[NEDGE];
__device__ int      d_is64;

__device__ __forceinline__ float gelu_fast(float x) {
    float x2 = x * x;
    float inner = x * fmaf(0.0356774081f, x2, 0.7978845608f);
    float t;
    asm("tanh.approx.f32 %0, %1;" : "=f"(t) : "f"(inner));
    float hx = 0.5f * x;
    return fmaf(hx, t, hx);
}
__device__ __forceinline__ uint32_t gelu_h2(uint32_t xu) {
    __half2 x = *(__half2*)&xu;
    const __half2 c1 = __floats2half2_rn(0.0356774081f, 0.0356774081f);
    const __half2 c0 = __floats2half2_rn(0.7978845608f, 0.7978845608f);
    const __half2 hf = __floats2half2_rn(0.5f, 0.5f);
    __half2 x2 = __hmul2(x, x);
    __half2 inner = __hmul2(x, __hfma2(c1, x2, c0));
    uint32_t tu;
    asm("tanh.approx.f16x2 %0, %1;" : "=r"(tu) : "r"(*(uint32_t*)&inner));
    __half2 hx = __hmul2(hf, x);
    __half2 res = __hfma2(hx, *(__half2*)&tu, hx);
    return *(uint32_t*)&res;
}
__device__ __forceinline__ void mma_fp16(float* d, const uint32_t* a, const uint32_t* b) {
    asm volatile("mma.sync.aligned.m16n8k16.row.col.f32.f16.f16.f32 "
                 "{%0,%1,%2,%3}, {%4,%5,%6,%7}, {%8,%9}, {%0,%1,%2,%3};"
                 : "+f"(d[0]), "+f"(d[1]), "+f"(d[2]), "+f"(d[3])
                 : "r"(a[0]), "r"(a[1]), "r"(a[2]), "r"(a[3]), "r"(b[0]), "r"(b[1]));
}
__device__ __forceinline__ uint32_t pack_h2(float a, float b) {
    __half2 h = __floats2half2_rn(a, b);
    return *(uint32_t*)&h;
}
__device__ __forceinline__ float2 unpack_h2(uint32_t u) {
    return __half22float2(*(__half2*)&u);
}

#define H_STRIDE 36     // half2 words per row (32 data + 4 pad)
#define W_STRIDE 72     // half2 words per k-pair row of W (64 data + 8 pad)
#define C_STRIDE 68     // fp32 staging stride

// ---------------- k_detect ----------------
__global__ void __launch_bounds__(256) k_detect(const void* __restrict__ ei) {
    int t = threadIdx.x;
#pragma unroll
    for (int r = 0; r < 32; r++)
        ((int4*)d_deg)[t + 256 * r] = make_int4(0, 0, 0, 0);
    __shared__ int bad;
    if (t == 0) bad = 0;
    __syncthreads();
    if (t < 128) {
        long long v = ((const long long*)ei)[t];
        if (v < 0 || v >= NPTS) atomicOr(&bad, 1);
    }
    __syncthreads();
    if (t == 0) d_is64 = bad ? 0 : 1;
}

// ---------------- k_count ----------------
__global__ void k_count(const void* __restrict__ ei) {
    int e = blockIdx.x * blockDim.x + threadIdx.x;
    if (e < NEDGE) {
        int dd = d_is64 ? (int)((const long long*)ei)[NEDGE + e]
                        : ((const int*)ei)[NEDGE + e];
        atomicAdd(&d_deg[dd], 1);
    }
}

// ---------------- k_scan ----------------
__global__ void __launch_bounds__(1024) k_scan() {
    __shared__ int wsum[32];
    int t = threadIdx.x, lane = t & 31, warp = t >> 5;
    int base = t * 32;
    int v[32];
    int s = 0;
#pragma unroll
    for (int i = 0; i < 32; i++) { v[i] = d_deg[base + i]; s += v[i]; }
    int sc = s;
#pragma unroll
    for (int o = 1; o < 32; o <<= 1) {
        int n = __shfl_up_sync(0xffffffffu, sc, o);
        if (lane >= o) sc += n;
    }
    if (lane == 31) wsum[warp] = sc;
    __syncthreads();
    if (warp == 0) {
        int ws = wsum[lane];
#pragma unroll
        for (int o = 1; o < 32; o <<= 1) {
            int n = __shfl_up_sync(0xffffffffu, ws, o);
            if (lane >= o) ws += n;
        }
        wsum[lane] = ws;
    }
    __syncthreads();
    int off = (warp > 0 ? wsum[warp - 1] : 0) + (sc - s);
#pragma unroll
    for (int i = 0; i < 32; i++) {
        d_off[base + i] = off;
        d_cursor[base + i] = off;
        d_invc[base + i] = 1.0f / fmaxf((float)v[i], 1.0f);
        off += v[i];
    }
}

// ---------------- k_sortz: src-only CSR fill ----------------
__global__ void __launch_bounds__(256) k_sortz(const void* __restrict__ ei) {
    int e = blockIdx.x * 256 + threadIdx.x;
    int is64 = d_is64;
    int ss, dd;
    if (is64) {
        ss = (int)((const long long*)ei)[e];
        dd = (int)((const long long*)ei)[NEDGE + e];
    } else {
        ss = ((const int*)ei)[e];
        dd = ((const int*)ei)[NEDGE + e];
    }
    int p = atomicAdd(&d_cursor[dd], 1);
    d_ssrc[p] = ss;
}

// ---------------- k_lift: fp16 mma, 128 items/block ----------------
#define LIFT_IN   0
#define LIFT_B2   3072
#define LIFT_TS   3328                       // u32 packed (18432) / f32 C staging (34816)
#define LIFT_WS   (3328 + 34816)
#define LIFT_SMEM (LIFT_WS + 9216)

__global__ void __launch_bounds__(256) k_lift(
    const float* __restrict__ x, const float* __restrict__ pos,
    const float* __restrict__ w1, const float* __restrict__ b1,
    const float* __restrict__ w2, const float* __restrict__ b2)
{
    extern __shared__ char smem[];
    float*    in_s = (float*)(smem + LIFT_IN);
    float*    b2_s = (float*)(smem + LIFT_B2);
    uint32_t* t_s  = (uint32_t*)(smem + LIFT_TS);
    float*    t_sf = (float*)(smem + LIFT_TS);
    uint32_t* w_s  = (uint32_t*)(smem + LIFT_WS);

    int t = threadIdx.x;
    int item0 = blockIdx.x * 128;

    for (int idx = t; idx < 640; idx += 256) {
        int j = idx / 5, i = idx % 5;
        int item = item0 + j;
        int b = item >> 15, n = item & (NPTS - 1);
        in_s[j * 6 + i] = (i < 3) ? x[((size_t)b * NPTS + n) * 3 + i] : pos[n * 2 + (i - 3)];
    }
    if (t < 64) b2_s[t] = b2[t];
    __syncthreads();

    int c2 = t & 31, jg = t >> 5;        // phase1: col pair, 8 groups x 16 rows
    int w  = t >> 5, lane = t & 31;
    int r  = lane >> 2, c4 = lane & 3;
    int m0 = w * 16;

    float acc[8][4];
#pragma unroll
    for (int j = 0; j < 8; j++)
        acc[j][0] = acc[j][1] = acc[j][2] = acc[j][3] = 0.f;

    for (int ch = 0; ch < 4; ch++) {
        int cc0 = ch * 64 + 2 * c2, cc1 = cc0 + 1;
        float wa0 = w1[cc0], wa1 = w1[LIFTD + cc0], wa2 = w1[2 * LIFTD + cc0];
        float wa3 = w1[3 * LIFTD + cc0], wa4 = w1[4 * LIFTD + cc0];
        float wb0 = w1[cc1], wb1 = w1[LIFTD + cc1], wb2 = w1[2 * LIFTD + cc1];
        float wb3 = w1[3 * LIFTD + cc1], wb4 = w1[4 * LIFTD + cc1];
        float bc0 = b1[cc0], bc1 = b1[cc1];
#pragma unroll 4
        for (int rr = 0; rr < 16; rr++) {
            int row = jg * 16 + rr;
            const float* in = in_s + row * 6;
            float v0 = bc0 + in[0] * wa0 + in[1] * wa1 + in[2] * wa2 + in[3] * wa3 + in[4] * wa4;
            float v1 = bc1 + in[0] * wb0 + in[1] * wb1 + in[2] * wb2 + in[3] * wb3 + in[4] * wb4;
            t_s[row * H_STRIDE + c2] = pack_h2(gelu_fast(v0), gelu_fast(v1));
        }
        for (int idx = t; idx < 2048; idx += 256) {
            int i = idx >> 6, n = idx & 63;
            w_s[i * W_STRIDE + n] = pack_h2(w2[(ch * 64 + 2 * i) * HID + n],
                                            w2[(ch * 64 + 2 * i + 1) * HID + n]);
        }
        __syncthreads();

#pragma unroll
        for (int kk = 0; kk < 4; kk++) {
            uint32_t a[4];
            a[0] = t_s[(m0 + r)     * H_STRIDE + kk * 8 + c4];
            a[1] = t_s[(m0 + r + 8) * H_STRIDE + kk * 8 + c4];
            a[2] = t_s[(m0 + r)     * H_STRIDE + kk * 8 + c4 + 4];
            a[3] = t_s[(m0 + r + 8) * H_STRIDE + kk * 8 + c4 + 4];
#pragma unroll
            for (int j = 0; j < 8; j++) {
                uint32_t bb[2];
                bb[0] = w_s[(kk * 8 + c4)     * W_STRIDE + j * 8 + r];
                bb[1] = w_s[(kk * 8 + c4 + 4) * W_STRIDE + j * 8 + r];
                mma_fp16(acc[j], a, bb);
            }
        }
        __syncthreads();
    }

#pragma unroll
    for (int j = 0; j < 8; j++) {
        int col = j * 8 + c4 * 2;
        float b0 = b2_s[col], b1v = b2_s[col + 1];
        *(float2*)(t_sf + (m0 + r)     * C_STRIDE + col) = make_float2(acc[j][0] + b0, acc[j][1] + b1v);
        *(float2*)(t_sf + (m0 + r + 8) * C_STRIDE + col) = make_float2(acc[j][2] + b0, acc[j][3] + b1v);
    }
    __syncthreads();
    for (int idx = t; idx < 8192; idx += 256) {
        int row = idx >> 6, cc = idx & 63;
        d_h[(size_t)(item0 + row) * 64 + cc] = t_sf[row * C_STRIDE + cc];
    }
}

// ---------------- k_APd: fp16 mma, fused update + Pd + A ------------------
#define APD_POS  0
#define APD_PW   1024
#define APD_KB2  2048
#define APD_HS   2304
#define APD_WS   (2304 + 18432)
#define APD_SMEM (APD_WS + 9216)

__global__ void __launch_bounds__(256) k_APd(
    const float* __restrict__ pos, const float* __restrict__ kW1_l,
    const float* __restrict__ kb1_l, const float* __restrict__ kW2_p,
    const float* __restrict__ kb2_p, int do_upd)
{
    extern __shared__ char smem[];
    float*    pos_s  = (float*)(smem + APD_POS);
    float*    pw_s   = (float*)(smem + APD_PW);
    float*    kb2_s  = (float*)(smem + APD_KB2);
    uint32_t* h_s    = (uint32_t*)(smem + APD_HS);
    uint32_t* w_s    = (uint32_t*)(smem + APD_WS);

    int t = threadIdx.x;
    int item0 = blockIdx.x * 128;
    int w = t >> 5, lane = t & 31;
    int r = lane >> 2, c4 = lane & 3;
    int m0 = w * 16;

    if (t < 256) {
        int j = t >> 1, i = t & 1;
        int n = (item0 + j) & (NPTS - 1);
        pos_s[j * 2 + i] = pos[n * 2 + i];
    }
    if (t < 256) pw_s[t] = kW1_l[t];
    if (do_upd && t < 64) kb2_s[t] = kb2_p[t];

    if (do_upd) {
        // stage G packed (warp-local rows)
#pragma unroll 4
        for (int i = 0; i < 16; i++) {
            int row = m0 + i;
            float2 g = *(float2*)(d_agg + (size_t)(item0 + row) * 64 + lane * 2);
            h_s[row * H_STRIDE + lane] = pack_h2(g.x, g.y);
        }
        for (int idx = t; idx < 2048; idx += 256) {
            int i = idx >> 6, n = idx & 63;
            w_s[i * W_STRIDE + n] = pack_h2(kW2_p[(2 * i) * 64 + n], kW2_p[(2 * i + 1) * 64 + n]);
        }
        __syncthreads();

        // MMA1: G @ W2 (fp16)
        float acc[8][4];
#pragma unroll
        for (int j = 0; j < 8; j++)
            acc[j][0] = acc[j][1] = acc[j][2] = acc[j][3] = 0.f;
#pragma unroll
        for (int kk = 0; kk < 4; kk++) {
            uint32_t a[4];
            a[0] = h_s[(m0 + r)     * H_STRIDE + kk * 8 + c4];
            a[1] = h_s[(m0 + r + 8) * H_STRIDE + kk * 8 + c4];
            a[2] = h_s[(m0 + r)     * H_STRIDE + kk * 8 + c4 + 4];
            a[3] = h_s[(m0 + r + 8) * H_STRIDE + kk * 8 + c4 + 4];
#pragma unroll
            for (int j = 0; j < 8; j++) {
                uint32_t bb[2];
                bb[0] = w_s[(kk * 8 + c4)     * W_STRIDE + j * 8 + r];
                bb[1] = w_s[(kk * 8 + c4 + 4) * W_STRIDE + j * 8 + r];
                mma_fp16(acc[j], a, bb);
            }
        }
        __syncwarp();

        // h_new = h + (acc + deg*kb2)*invc; write d_h; restage packed
        int nA = (item0 + m0 + r) & (NPTS - 1);
        int nB = (item0 + m0 + r + 8) & (NPTS - 1);
        float iA = d_invc[nA], dA = (float)d_deg[nA];
        float iB = d_invc[nB], dB = (float)d_deg[nB];
        size_t gA = (size_t)(item0 + m0 + r) * 64;
        size_t gB = (size_t)(item0 + m0 + r + 8) * 64;
#pragma unroll
        for (int j = 0; j < 8; j++) {
            int col = j * 8 + c4 * 2;
            float k0 = kb2_s[col], k1 = kb2_s[col + 1];
            float2 hA = *(float2*)(d_h + gA + col);
            float2 hB = *(float2*)(d_h + gB + col);
            float a0 = hA.x + (acc[j][0] + dA * k0) * iA;
            float a1 = hA.y + (acc[j][1] + dA * k1) * iA;
            float b0 = hB.x + (acc[j][2] + dB * k0) * iB;
            float b1 = hB.y + (acc[j][3] + dB * k1) * iB;
            *(float2*)(d_h + gA + col) = make_float2(a0, a1);
            *(float2*)(d_h + gB + col) = make_float2(b0, b1);
            h_s[(m0 + r) * H_STRIDE + j * 4 + c4]     = pack_h2(a0, a1);
            h_s[(m0 + r + 8) * H_STRIDE + j * 4 + c4] = pack_h2(b0, b1);
        }
        __syncthreads();
    } else {
        for (int idx = t; idx < 4096; idx += 256) {
            int row = idx >> 5, c2 = idx & 31;
            float2 hv = *(float2*)(d_h + (size_t)(item0 + row) * 64 + c2 * 2);
            h_s[row * H_STRIDE + c2] = pack_h2(hv.x, hv.y);
        }
    }

    // stage W1[4:68] packed
    for (int idx = t; idx < 2048; idx += 256) {
        int i = idx >> 6, n = idx & 63;
        w_s[i * W_STRIDE + n] = pack_h2(kW1_l[(4 + 2 * i) * 64 + n], kW1_l[(4 + 2 * i + 1) * 64 + n]);
    }
    __syncthreads();

    // Pd (b0 blocks cover all n)
    if (item0 < NPTS) {
        for (int idx = t; idx < 4096; idx += 256) {
            int row = idx >> 5, c2 = idx & 31;
            int n = item0 + row, c = c2 * 2;
            float p0 = pos_s[row * 2], p1 = pos_s[row * 2 + 1];
            float v0 = kb1_l[c]     + p0 * pw_s[128 + c]     + p1 * pw_s[192 + c];
            float v1 = kb1_l[c + 1] + p0 * pw_s[128 + c + 1] + p1 * pw_s[192 + c + 1];
            d_Pdh[(size_t)n * 32 + c2] = pack_h2(v0, v1);
        }
    }

    // MMA2: h @ W1[4:68] -> A (fp16)
    float acc[8][4];
#pragma unroll
    for (int j = 0; j < 8; j++)
        acc[j][0] = acc[j][1] = acc[j][2] = acc[j][3] = 0.f;
#pragma unroll
    for (int kk = 0; kk < 4; kk++) {
        uint32_t a[4];
        a[0] = h_s[(m0 + r)     * H_STRIDE + kk * 8 + c4];
        a[1] = h_s[(m0 + r + 8) * H_STRIDE + kk * 8 + c4];
        a[2] = h_s[(m0 + r)     * H_STRIDE + kk * 8 + c4 + 4];
        a[3] = h_s[(m0 + r + 8) * H_STRIDE + kk * 8 + c4 + 4];
#pragma unroll
        for (int j = 0; j < 8; j++) {
            uint32_t bb[2];
            bb[0] = w_s[(kk * 8 + c4)     * W_STRIDE + j * 8 + r];
            bb[1] = w_s[(kk * 8 + c4 + 4) * W_STRIDE + j * 8 + r];
            mma_fp16(acc[j], a, bb);
        }
    }
    __syncwarp();   // warp-local rows: MMA reads done before overwrite

    float p00 = pos_s[(m0 + r) * 2],     p01 = pos_s[(m0 + r) * 2 + 1];
    float p10 = pos_s[(m0 + r + 8) * 2], p11 = pos_s[(m0 + r + 8) * 2 + 1];
#pragma unroll
    for (int j = 0; j < 8; j++) {
        int col = j * 8 + c4 * 2;
        float w00 = pw_s[col], w01 = pw_s[col + 1];
        float w10 = pw_s[64 + col], w11 = pw_s[64 + col + 1];
        h_s[(m0 + r) * H_STRIDE + j * 4 + c4] =
            pack_h2(acc[j][0] + p00 * w00 + p01 * w10, acc[j][1] + p00 * w01 + p01 * w11);
        h_s[(m0 + r + 8) * H_STRIDE + j * 4 + c4] =
            pack_h2(acc[j][2] + p10 * w00 + p11 * w10, acc[j][3] + p10 * w01 + p11 * w11);
    }
    __syncthreads();
    for (int idx = t; idx < 4096; idx += 256) {
        int row = idx >> 5, cc = idx & 31;
        d_Ah[(size_t)(item0 + row) * 32 + cc] = h_s[row * H_STRIDE + cc];
    }
}

// ---------------- k_edge: CSR warp-per-node, no atomics -------------------
__global__ void __launch_bounds__(256) k_edge()
{
    int wg = blockIdx.x * 8 + (threadIdx.x >> 5);
    int lane = threadIdx.x & 31;
    const uint32_t* A0 = d_Ah;
    const uint32_t* A1 = d_Ah + (size_t)NPTS * 32;

#pragma unroll
    for (int j = 0; j < 2; j++) {
        int n = wg * 2 + j;
        int len   = d_deg[n];
        int start = d_off[n];
        uint32_t pd = d_Pdh[(size_t)n * 32 + lane];
        __half2 pdh = *(__half2*)&pd;
        float a00 = 0.f, a01 = 0.f, a10 = 0.f, a11 = 0.f;
#pragma unroll 4
        for (int e = 0; e < len; e++) {
            int ss = __ldg(&d_ssrc[start + e]);
            uint32_t av0 = __ldg(&A0[(size_t)ss * 32 + lane]);
            uint32_t av1 = __ldg(&A1[(size_t)ss * 32 + lane]);
            __half2 s0 = __hadd2(*(__half2*)&av0, pdh);
            __half2 s1 = __hadd2(*(__half2*)&av1, pdh);
            float2 f0 = unpack_h2(gelu_h2(*(uint32_t*)&s0));
            float2 f1 = unpack_h2(gelu_h2(*(uint32_t*)&s1));
            a00 += f0.x; a01 += f0.y; a10 += f1.x; a11 += f1.y;
        }
        *(float2*)(d_agg + (size_t)n * 64 + lane * 2) = make_float2(a00, a01);
        *(float2*)(d_agg + (size_t)(NPTS + n) * 64 + lane * 2) = make_float2(a10, a11);
    }
}

// ---------------- k_proj: fp16 mma, fused update + proj MLP ---------------
#define PROJ_HS   0
#define PROJ_WS   18432
#define PROJ_W2   (18432 + 9216)
#define PROJ_B1   (PROJ_W2 + 1024)
#define PROJ_KB2  (PROJ_B1 + 1024)
#define PROJ_SMEM (PROJ_KB2 + 256)

__global__ void __launch_bounds__(256) k_proj(
    const float* __restrict__ w1, const float* __restrict__ b1,
    const float* __restrict__ w2, const float* __restrict__ b2,
    const float* __restrict__ kW2_p, const float* __restrict__ kb2_p,
    float* __restrict__ out)
{
    extern __shared__ char smem[];
    uint32_t* h_s   = (uint32_t*)(smem + PROJ_HS);
    uint32_t* w_s   = (uint32_t*)(smem + PROJ_WS);
    float*    w2_s  = (float*)(smem + PROJ_W2);
    float*    b1_s  = (float*)(smem + PROJ_B1);
    float*    kb2_s = (float*)(smem + PROJ_KB2);

    int t = threadIdx.x;
    int item0 = blockIdx.x * 128;
    int w = t >> 5, lane = t & 31;
    int r = lane >> 2, c4 = lane & 3;
    int m0 = w * 16;

    w2_s[t] = w2[t];
    b1_s[t] = b1[t];
    if (t < 64) kb2_s[t] = kb2_p[t];

#pragma unroll 4
    for (int i = 0; i < 16; i++) {
        int row = m0 + i;
        float2 g = *(float2*)(d_agg + (size_t)(item0 + row) * 64 + lane * 2);
        h_s[row * H_STRIDE + lane] = pack_h2(g.x, g.y);
    }
    for (int idx = t; idx < 2048; idx += 256) {
        int i = idx >> 6, n = idx & 63;
        w_s[i * W_STRIDE + n] = pack_h2(kW2_p[(2 * i) * 64 + n], kW2_p[(2 * i + 1) * 64 + n]);
    }
    __syncthreads();

    {
        float acc[8][4];
#pragma unroll
        for (int j = 0; j < 8; j++)
            acc[j][0] = acc[j][1] = acc[j][2] = acc[j][3] = 0.f;
#pragma unroll
        for (int kk = 0; kk < 4; kk++) {
            uint32_t a[4];
            a[0] = h_s[(m0 + r)     * H_STRIDE + kk * 8 + c4];
            a[1] = h_s[(m0 + r + 8) * H_STRIDE + kk * 8 + c4];
            a[2] = h_s[(m0 + r)     * H_STRIDE + kk * 8 + c4 + 4];
            a[3] = h_s[(m0 + r + 8) * H_STRIDE + kk * 8 + c4 + 4];
#pragma unroll
            for (int j = 0; j < 8; j++) {
                uint32_t bb[2];
                bb[0] = w_s[(kk * 8 + c4)     * W_STRIDE + j * 8 + r];
                bb[1] = w_s[(kk * 8 + c4 + 4) * W_STRIDE + j * 8 + r];
                mma_fp16(acc[j], a, bb);
            }
        }
        __syncwarp();

        int nA = (item0 + m0 + r) & (NPTS - 1);
        int nB = (item0 + m0 + r + 8) & (NPTS - 1);
        float iA = d_invc[nA], dA = (float)d_deg[nA];
        float iB = d_invc[nB], dB = (float)d_deg[nB];
        size_t gA = (size_t)(item0 + m0 + r) * 64;
        size_t gB = (size_t)(item0 + m0 + r + 8) * 64;
#pragma unroll
        for (int j = 0; j < 8; j++) {
            int col = j * 8 + c4 * 2;
            float k0 = kb2_s[col], k1 = kb2_s[col + 1];
            float2 hA = *(float2*)(d_h + gA + col);
            float2 hB = *(float2*)(d_h + gB + col);
            h_s[(m0 + r) * H_STRIDE + j * 4 + c4] =
                pack_h2(hA.x + (acc[j][0] + dA * k0) * iA, hA.y + (acc[j][1] + dA * k1) * iA);
            h_s[(m0 + r + 8) * H_STRIDE + j * 4 + c4] =
                pack_h2(hB.x + (acc[j][2] + dB * k0) * iB, hB.y + (acc[j][3] + dB * k1) * iB);
        }
        __syncwarp();
    }

    uint32_t a[4][4];
#pragma unroll
    for (int kk = 0; kk < 4; kk++) {
        a[kk][0] = h_s[(m0 + r)     * H_STRIDE + kk * 8 + c4];
        a[kk][1] = h_s[(m0 + r + 8) * H_STRIDE + kk * 8 + c4];
        a[kk][2] = h_s[(m0 + r)     * H_STRIDE + kk * 8 + c4 + 4];
        a[kk][3] = h_s[(m0 + r + 8) * H_STRIDE + kk * 8 + c4 + 4];
    }

    float sum0 = 0.f, sum1 = 0.f;
    for (int ch = 0; ch < 4; ch++) {
        __syncthreads();
        for (int idx = t; idx < 2048; idx += 256) {
            int i = idx >> 6, n = idx & 63;
            w_s[i * W_STRIDE + n] = pack_h2(w1[(2 * i) * 256 + ch * 64 + n],
                                            w1[(2 * i + 1) * 256 + ch * 64 + n]);
        }
        __syncthreads();

        float acc[8][4];
#pragma unroll
        for (int j = 0; j < 8; j++)
            acc[j][0] = acc[j][1] = acc[j][2] = acc[j][3] = 0.f;
#pragma unroll
        for (int kk = 0; kk < 4; kk++) {
#pragma unroll
            for (int j = 0; j < 8; j++) {
                uint32_t bb[2];
                bb[0] = w_s[(kk * 8 + c4)     * W_STRIDE + j * 8 + r];
                bb[1] = w_s[(kk * 8 + c4 + 4) * W_STRIDE + j * 8 + r];
                mma_fp16(acc[j], a[kk], bb);
            }
        }
#pragma unroll
        for (int j = 0; j < 8; j++) {
            int col = ch * 64 + j * 8 + c4 * 2;
            sum0 += gelu_fast(acc[j][0] + b1_s[col]) * w2_s[col]
                  + gelu_fast(acc[j][1] + b1_s[col + 1]) * w2_s[col + 1];
            sum1 += gelu_fast(acc[j][2] + b1_s[col]) * w2_s[col]
                  + gelu_fast(acc[j][3] + b1_s[col + 1]) * w2_s[col + 1];
        }
    }

    sum0 += __shfl_xor_sync(0xffffffffu, sum0, 1);
    sum0 += __shfl_xor_sync(0xffffffffu, sum0, 2);
    sum1 += __shfl_xor_sync(0xffffffffu, sum1, 1);
    sum1 += __shfl_xor_sync(0xffffffffu, sum1, 2);
    if (c4 == 0) {
        float bb = b2[0];
        out[item0 + m0 + r]     = sum0 + bb;
        out[item0 + m0 + r + 8] = sum1 + bb;
    }
}

// ---------------- launch ----------------
extern "C" void kernel_launch(void* const* d_in, const int* in_sizes, int n_in,
                              void* d_out, int out_size) {
    (void)in_sizes; (void)n_in; (void)out_size;
    const float* x    = (const float*)d_in[0];
    const float* pos  = (const float*)d_in[1];
    const void*  ei   = d_in[2];
    const float* lw1  = (const float*)d_in[3];
    const float* lb1  = (const float*)d_in[4];
    const float* lw2  = (const float*)d_in[5];
    const float* lb2  = (const float*)d_in[6];
    const float* kW1  = (const float*)d_in[7];
    const float* kb1  = (const float*)d_in[8];
    const float* kW2  = (const float*)d_in[9];
    const float* kb2  = (const float*)d_in[10];
    const float* pw1  = (const float*)d_in[11];
    const float* pb1  = (const float*)d_in[12];
    const float* pw2  = (const float*)d_in[13];
    const float* pb2  = (const float*)d_in[14];
    float* out = (float*)d_out;

    cudaFuncSetAttribute(k_lift, cudaFuncAttributeMaxDynamicSharedMemorySize, LIFT_SMEM);
    cudaFuncSetAttribute(k_APd,  cudaFuncAttributeMaxDynamicSharedMemorySize, APD_SMEM);
    cudaFuncSetAttribute(k_proj, cudaFuncAttributeMaxDynamicSharedMemorySize, PROJ_SMEM);

    // ordering: profiled launch index 3 = k_APd (layer 0)
    k_detect<<<1, 256>>>(ei);                                                       // 0
    k_count<<<NEDGE / 256, 256>>>(ei);                                              // 1
    k_lift<<<(NBATCH * NPTS) / 128, 256, LIFT_SMEM>>>(x, pos, lw1, lb1, lw2, lb2);  // 2
    k_APd<<<(NBATCH * NPTS) / 128, 256, APD_SMEM>>>(pos, kW1, kb1, kW2, kb2, 0);    // 3
    k_scan<<<1, 1024>>>();                                                          // 4
    k_sortz<<<NEDGE / 256, 256>>>(ei);                                              // 5
    k_edge<<<NPTS / 16, 256>>>();                                                   // 6

    for (int l = 1; l < NLAYER; l++) {
        const float* W1l = kW1 + (size_t)l * 68 * 64;
        const float* b1l = kb1 + (size_t)l * 64;
        const float* W2p = kW2 + (size_t)(l - 1) * 64 * 64;
        const float* b2p = kb2 + (size_t)(l - 1) * 64;
        k_APd<<<(NBATCH * NPTS) / 128, 256, APD_SMEM>>>(pos, W1l, b1l, W2p, b2p, 1);
        k_edge<<<NPTS / 16, 256>>>();
    }

    k_proj<<<(NBATCH * NPTS) / 128, 256, PROJ_SMEM>>>(
        pw1, pb1, pw2, pb2,
        kW2 + (size_t)(NLAYER - 1) * 64 * 64, kb2 + (size_t)(NLAYER - 1) * 64, out);
}